// round 12
// baseline (speedup 1.0000x reference)
#include <cuda_runtime.h>
#include <cuda_fp16.h>
#include <cstdint>
#include <math.h>

#define B_ 8
#define C_ 256
#define N_ 4096
#define O_ 128

// Scratch (__device__ globals: allocation-free rule).
__device__ __half d_th [(size_t)B_ * N_ * O_];   // theta * log2(e), fp16
__device__ __half d_ph [(size_t)B_ * N_ * O_];
__device__ __half d_g  [(size_t)B_ * N_ * O_];
__device__ __half d_y16[(size_t)B_ * N_ * O_];
__device__ __half d_w16[3 * O_ * C_];

__device__ __forceinline__ uint32_t smem_u32(const void* p) {
    uint32_t a;
    asm("{ .reg .u64 t; cvta.to.shared.u64 t, %1; cvt.u32.u64 %0, t; }" : "=r"(a) : "l"(p));
    return a;
}

#define MMAF16(c, a, b0v, b1v) asm volatile( \
    "mma.sync.aligned.m16n8k16.row.col.f32.f16.f16.f32 " \
    "{%0,%1,%2,%3}, {%4,%5,%6,%7}, {%8,%9}, {%0,%1,%2,%3};" \
    : "+f"((c)[0]), "+f"((c)[1]), "+f"((c)[2]), "+f"((c)[3]) \
    : "r"((a)[0]), "r"((a)[1]), "r"((a)[2]), "r"((a)[3]), "r"(b0v), "r"(b1v))

// fp16-accumulator MMA (C/D are 2 x fp16x2 regs)
#define MMAH(c, a, b0v, b1v) asm volatile( \
    "mma.sync.aligned.m16n8k16.row.col.f16.f16.f16.f16 " \
    "{%0,%1}, {%2,%3,%4,%5}, {%6,%7}, {%0,%1};" \
    : "+r"((c)[0]), "+r"((c)[1]) \
    : "r"((a)[0]), "r"((a)[1]), "r"((a)[2]), "r"((a)[3]), "r"(b0v), "r"(b1v))

#define LDSM4(r0, r1, r2, r3, addr)  asm volatile("ldmatrix.sync.aligned.m8n8.x4.shared.b16 {%0,%1,%2,%3}, [%4];" : "=r"(r0), "=r"(r1), "=r"(r2), "=r"(r3) : "r"(addr))
#define LDSM4T(r0, r1, r2, r3, addr) asm volatile("ldmatrix.sync.aligned.m8n8.x4.trans.shared.b16 {%0,%1,%2,%3}, [%4];" : "=r"(r0), "=r"(r1), "=r"(r2), "=r"(r3) : "r"(addr))
#define CP16(dst, src)   asm volatile("cp.async.cg.shared.global [%0], [%1], 16;" :: "r"(dst), "l"(src))
#define CP_COMMIT()      asm volatile("cp.async.commit_group;" ::: "memory")
#define CP_WAIT0()       asm volatile("cp.async.wait_group 0;" ::: "memory")
#define CP_WAIT1()       asm volatile("cp.async.wait_group 1;" ::: "memory")
#define EX2H2(r)         asm("ex2.approx.f16x2 %0, %0;" : "+r"(r))
#define HMUL2(d, s)      asm("mul.rn.f16x2 %0, %0, %1;" : "+r"(d) : "r"(s))

__device__ __forceinline__ uint32_t h2pair(float a, float b) {
    uint32_t r;
    asm("cvt.rn.f16x2.f32 %0, %1, %2;" : "=r"(r) : "f"(b), "f"(a));
    return r;
}

#define PITCH 272
#define LOG2E 1.4426950408889634f
#define ONESH2 0x3C003C00u

// ---------------------------------------------------------------------------
// Kernel 0: W -> fp16 once.
// ---------------------------------------------------------------------------
__global__ void setup_kernel(const float* __restrict__ wt,
                             const float* __restrict__ wp,
                             const float* __restrict__ wg)
{
    const int z = blockIdx.x;
    const float* W = (z == 0) ? wt : (z == 1) ? wp : wg;
    __half* out = d_w16 + (size_t)z * O_ * C_;
    for (int i = threadIdx.x; i < O_ * C_ / 4; i += blockDim.x) {
        float4 w = *(const float4*)(W + i * 4);
        *(uint32_t*)(out + i * 4)     = h2pair(w.x, w.y);
        *(uint32_t*)(out + i * 4 + 2) = h2pair(w.z, w.w);
    }
}

// ---------------------------------------------------------------------------
// Kernel 1: projections, single fp16 GEMM.  theta gets *LOG2E.
// grid (32 n, 8 b, 3 z), 256 thr.
// ---------------------------------------------------------------------------
#define PJ_WH 0
#define PJ_X  67584
#define PJ_XBUF 8704
#define PJ_PW 528
#define PROJ_SMEM 84992

__global__ __launch_bounds__(256, 1) void proj_kernel(
    const float* __restrict__ x,
    const float* __restrict__ bt, const float* __restrict__ bp,
    const float* __restrict__ bg)
{
    extern __shared__ __align__(128) char smem[];
    const uint32_t sb = smem_u32(smem);
    const int tid = threadIdx.x;
    const int wid = tid >> 5, lane = tid & 31;
    const int b = blockIdx.y, n0 = blockIdx.x * 128, z = blockIdx.z;
    const float* bias = (z == 0) ? bt : (z == 1) ? bp : bg;
    __half* outp = (z == 0) ? d_th : (z == 1) ? d_ph : d_g;
    const __half* Wg = d_w16 + (size_t)z * O_ * C_;
    const float osc = (z == 0) ? LOG2E : 1.f;

#pragma unroll
    for (int r = 0; r < 16; r++) {
        int idx = tid + r * 256;
        int o = idx >> 5, ch = idx & 31;
        CP16(sb + PJ_WH + (uint32_t)o * PJ_PW + ch * 16, Wg + (size_t)o * C_ + ch * 8);
    }
    CP_COMMIT();

    float4 xr[4];
    auto ldg_chunk = [&](int ck) {
#pragma unroll
        for (int r = 0; r < 4; r++) {
            int idx = tid + r * 256;
            int cc = idx >> 5, nv = (idx & 31) << 2;
            xr[r] = *(const float4*)(x + ((size_t)(b * C_ + ck * 32 + cc)) * N_ + n0 + nv);
        }
    };
    auto sts_chunk = [&](int buf) {
#pragma unroll
        for (int r = 0; r < 4; r++) {
            int idx = tid + r * 256;
            int cc = idx >> 5, nv = (idx & 31) << 2;
            float4 v = xr[r];
            uint32_t base = PJ_X + buf * PJ_XBUF + (uint32_t)cc * PITCH + nv * 2;
            *(uint32_t*)(smem + base)     = h2pair(v.x, v.y);
            *(uint32_t*)(smem + base + 4) = h2pair(v.z, v.w);
        }
    };

    ldg_chunk(0);
    CP_WAIT0();
    sts_chunk(0);
    __syncthreads();

    float acc[16][4];
#pragma unroll
    for (int t = 0; t < 16; t++)
#pragma unroll
        for (int i = 0; i < 4; i++) acc[t][i] = 0.f;

    const uint32_t xa_off = (uint32_t)((lane & 7) + ((lane >> 4) << 3)) * PITCH
                          + (uint32_t)(wid * 16 + (((lane >> 3) & 1) << 3)) * 2;
    const uint32_t wb4 = (uint32_t)(lane & 7) * PJ_PW + ((lane >> 3) & 1) * 16
                       + (uint32_t)(lane >> 4) * (8 * PJ_PW);

    for (int ck = 0; ck < 8; ck++) {
        const int buf = ck & 1;
        if (ck < 7) ldg_chunk(ck + 1);
        const uint32_t xb = sb + PJ_X + buf * PJ_XBUF + xa_off;
#pragma unroll
        for (int s = 0; s < 2; s++) {
            uint32_t ah[4];
            LDSM4T(ah[0], ah[1], ah[2], ah[3], xb + s * (16 * PITCH));
            const uint32_t wcol = sb + PJ_WH + wb4 + (uint32_t)(ck * 32 + s * 16) * 2;
#pragma unroll
            for (int jb2 = 0; jb2 < 8; jb2++) {
                uint32_t b0, b1, b2, b3;
                LDSM4(b0, b1, b2, b3, wcol + jb2 * (16 * PJ_PW));
                MMAF16(acc[2 * jb2],     ah, b0, b1);
                MMAF16(acc[2 * jb2 + 1], ah, b2, b3);
            }
        }
        if (ck < 7) sts_chunk(buf ^ 1);
        __syncthreads();
    }

    const size_t row0 = (size_t)b * N_ + n0 + wid * 16 + (lane >> 2);
#pragma unroll
    for (int jb = 0; jb < 16; jb++) {
        const int o = jb * 8 + 2 * (lane & 3);
        float2 b2 = *(const float2*)(bias + o);
        *(uint32_t*)(outp + row0 * O_ + o)       = h2pair((acc[jb][0] + b2.x) * osc, (acc[jb][1] + b2.y) * osc);
        *(uint32_t*)(outp + (row0 + 8) * O_ + o) = h2pair((acc[jb][2] + b2.x) * osc, (acc[jb][3] + b2.y) * osc);
    }
}

// ---------------------------------------------------------------------------
// Kernel 2: fp16 flash attention, BM=256, BK=64, 8 warps x 32 q-rows.
// Software-pipelined: PV lags one tile so its tensor work drains while the
// current tile's softmax (max-reduce + ex2) executes.  V triple-buffered.
// QK fp32-acc; softmax base-2 (ex2.f16x2); l via ones-MMA; PV fp16-acc.
// grid (16 q-tiles, 8 b), 256 threads.
// ---------------------------------------------------------------------------
#define BKA 64
#define NTA (N_ / BKA)
#define AK_OFF 0
#define AV_OFF 34816
#define KBUF   17408
#define ATTN_SMEM (34816 + 3 * 17408)

__global__ __launch_bounds__(256, 1) void attn_kernel()
{
    extern __shared__ __align__(128) char smem[];
    const uint32_t sb = smem_u32(smem);
    const int tid = threadIdx.x;
    const int wid = tid >> 5, lane = tid & 31;
    const int b = blockIdx.y, q0 = blockIdx.x * 256;

    // Q fragments: 2 M-blocks x 8 k-steps (theta already *log2e)
    uint32_t qh[2][8][4];
#pragma unroll
    for (int mb = 0; mb < 2; mb++) {
        const __half* Th = d_th + ((size_t)b * N_ + q0 + wid * 32 + mb * 16 + (lane >> 2)) * O_;
        const int c0 = 2 * (lane & 3);
#pragma unroll
        for (int s = 0; s < 8; s++) {
            qh[mb][s][0] = *(const uint32_t*)(Th + s * 16 + c0);
            qh[mb][s][1] = *(const uint32_t*)(Th + 8 * O_ + s * 16 + c0);
            qh[mb][s][2] = *(const uint32_t*)(Th + s * 16 + c0 + 8);
            qh[mb][s][3] = *(const uint32_t*)(Th + 8 * O_ + s * 16 + c0 + 8);
        }
    }

    const __half* Ph = d_ph + (size_t)b * N_ * O_;
    const __half* Vh = d_g  + (size_t)b * N_ * O_;

    const uint32_t kb4 = sb + AK_OFF + (lane & 7) * PITCH + ((lane >> 3) & 1) * 16
                       + (lane >> 4) * (8 * PITCH);
    const uint32_t vb4 = sb + AV_OFF + (lane & 7) * PITCH + ((lane >> 3) & 1) * (8 * PITCH)
                       + (lane >> 4) * 16;

    uint32_t acc2[2][16][2];   // fp16x2 accumulators
#pragma unroll
    for (int mb = 0; mb < 2; mb++)
#pragma unroll
        for (int k = 0; k < 16; k++) { acc2[mb][k][0] = 0u; acc2[mb][k][1] = 0u; }
    float lacc[2][4];
#pragma unroll
    for (int mb = 0; mb < 2; mb++)
#pragma unroll
        for (int i = 0; i < 4; i++) lacc[mb][i] = 0.f;
    float m0[2] = {-1e30f, -1e30f}, m1[2] = {-1e30f, -1e30f};
    uint32_t ah[2][4][4];      // P fragments of the PREVIOUS tile
    int vprev = 0;

    auto load_tile = [&](int jt) {
        const size_t k0 = (size_t)jt * BKA;
        const uint32_t koff = AK_OFF + (uint32_t)(jt & 1) * KBUF;
        const uint32_t voff = AV_OFF + (uint32_t)(jt % 3) * KBUF;
#pragma unroll
        for (int r = 0; r < 4; r++) {
            int idx = tid + r * 256;
            int k = idx >> 4, ch = idx & 15;
            uint32_t off = (uint32_t)k * PITCH + ch * 16;
            const size_t g = (k0 + k) * O_ + ch * 8;
            CP16(sb + koff + off, Ph + g);
            CP16(sb + voff + off, Vh + g);
        }
    };

    load_tile(0);
    CP_COMMIT();

    for (int j = 0; j < NTA; j++) {
        if (j + 1 < NTA) { load_tile(j + 1); CP_COMMIT(); CP_WAIT1(); }
        else            { CP_WAIT0(); }
        __syncthreads();

        // ---- QK(j): S = Q K^T, fp32 acc (base-2 logits) ----
        float S[16][4];
#pragma unroll
        for (int i = 0; i < 16; i++)
#pragma unroll
            for (int q = 0; q < 4; q++) S[i][q] = 0.f;
        const uint32_t kb = kb4 + (uint32_t)(j & 1) * KBUF;
#pragma unroll
        for (int s = 0; s < 8; s++) {
#pragma unroll
            for (int jb2 = 0; jb2 < 4; jb2++) {
                uint32_t b0, b1, b2, b3;
                LDSM4(b0, b1, b2, b3, kb + jb2 * (16 * PITCH) + s * 32);
                MMAF16(S[2 * jb2],         qh[0][s], b0, b1);
                MMAF16(S[2 * jb2 + 1],     qh[0][s], b2, b3);
                MMAF16(S[8 + 2 * jb2],     qh[1][s], b0, b1);
                MMAF16(S[8 + 2 * jb2 + 1], qh[1][s], b2, b3);
            }
        }

        // ---- PV(j-1): drains the tensor pipe while softmax(j) runs ----
        if (j > 0) {
            const uint32_t vb = vb4 + (uint32_t)vprev * KBUF;
#pragma unroll
            for (int s2 = 0; s2 < 4; s2++) {
                MMAF16(lacc[0], ah[0][s2], ONESH2, ONESH2);
                MMAF16(lacc[1], ah[1][s2], ONESH2, ONESH2);
#pragma unroll
                for (int t2 = 0; t2 < 8; t2++) {
                    uint32_t v0, v1, v2, v3;
                    LDSM4T(v0, v1, v2, v3, vb + s2 * (16 * PITCH) + t2 * 32);
                    MMAH(acc2[0][2 * t2],     ah[0][s2], v0, v1);
                    MMAH(acc2[0][2 * t2 + 1], ah[0][s2], v2, v3);
                    MMAH(acc2[1][2 * t2],     ah[1][s2], v0, v1);
                    MMAH(acc2[1][2 * t2 + 1], ah[1][s2], v2, v3);
                }
            }
        }

        // ---- softmax(j): max-reduce, ex2 -> ah, THEN rescale acc/l ----
#pragma unroll
        for (int mb = 0; mb < 2; mb++) {
            float mt0 = S[mb * 8][0], mt1 = S[mb * 8][2];
#pragma unroll
            for (int nb = 0; nb < 8; nb++) {
                mt0 = fmaxf(mt0, fmaxf(S[mb * 8 + nb][0], S[mb * 8 + nb][1]));
                mt1 = fmaxf(mt1, fmaxf(S[mb * 8 + nb][2], S[mb * 8 + nb][3]));
            }
            mt0 = fmaxf(mt0, __shfl_xor_sync(0xffffffffu, mt0, 1));
            mt0 = fmaxf(mt0, __shfl_xor_sync(0xffffffffu, mt0, 2));
            mt1 = fmaxf(mt1, __shfl_xor_sync(0xffffffffu, mt1, 1));
            mt1 = fmaxf(mt1, __shfl_xor_sync(0xffffffffu, mt1, 2));
            float mn0 = fmaxf(m0[mb], mt0), mn1 = fmaxf(m1[mb], mt1);
            float sc0 = exp2f(m0[mb] - mn0), sc1 = exp2f(m1[mb] - mn1);
            m0[mb] = mn0; m1[mb] = mn1;
            // ex2 first (overlaps PV(j-1) tensor drain); rescale after.
#pragma unroll
            for (int nb = 0; nb < 8; nb++) {
                const int i = mb * 8 + nb;
                uint32_t p0 = h2pair(S[i][0] - mn0, S[i][1] - mn0);
                uint32_t p1 = h2pair(S[i][2] - mn1, S[i][3] - mn1);
                EX2H2(p0);
                EX2H2(p1);
                ah[mb][nb >> 1][(nb & 1) * 2]     = p0;
                ah[mb][nb >> 1][(nb & 1) * 2 + 1] = p1;
            }
            uint32_t scp0 = h2pair(sc0, sc0), scp1 = h2pair(sc1, sc1);
#pragma unroll
            for (int k = 0; k < 16; k++) {
                HMUL2(acc2[mb][k][0], scp0);
                HMUL2(acc2[mb][k][1], scp1);
            }
            lacc[mb][0] *= sc0; lacc[mb][1] *= sc0;
            lacc[mb][2] *= sc1; lacc[mb][3] *= sc1;
        }
        vprev = j % 3;
        __syncthreads();
    }

    // ---- final PV(NTA-1) ----
    {
        const uint32_t vb = vb4 + (uint32_t)vprev * KBUF;
#pragma unroll
        for (int s2 = 0; s2 < 4; s2++) {
            MMAF16(lacc[0], ah[0][s2], ONESH2, ONESH2);
            MMAF16(lacc[1], ah[1][s2], ONESH2, ONESH2);
#pragma unroll
            for (int t2 = 0; t2 < 8; t2++) {
                uint32_t v0, v1, v2, v3;
                LDSM4T(v0, v1, v2, v3, vb + s2 * (16 * PITCH) + t2 * 32);
                MMAH(acc2[0][2 * t2],     ah[0][s2], v0, v1);
                MMAH(acc2[0][2 * t2 + 1], ah[0][s2], v2, v3);
                MMAH(acc2[1][2 * t2],     ah[1][s2], v0, v1);
                MMAH(acc2[1][2 * t2 + 1], ah[1][s2], v2, v3);
            }
        }
    }

    // epilogue: normalize by l (from ones-MMA), store y fp16
#pragma unroll
    for (int mb = 0; mb < 2; mb++) {
        const float inv0 = 1.f / lacc[mb][0];
        const float inv1 = 1.f / lacc[mb][2];
        const size_t row = (size_t)b * N_ + q0 + wid * 32 + mb * 16 + (lane >> 2);
#pragma unroll
        for (int k = 0; k < 16; k++) {
            const int col = (k >> 1) * 16 + (k & 1) * 8 + 2 * (lane & 3);
            __half2 h0 = *(__half2*)&acc2[mb][k][0];
            __half2 h1 = *(__half2*)&acc2[mb][k][1];
            *(uint32_t*)(d_y16 + row * O_ + col) =
                h2pair(__low2float(h0) * inv0, __high2float(h0) * inv0);
            *(uint32_t*)(d_y16 + (row + 8) * O_ + col) =
                h2pair(__low2float(h1) * inv1, __high2float(h1) * inv1);
        }
    }
}

// ---------------------------------------------------------------------------
// Kernel 3: out = x + BN(W_out y + b_out), single fp16 GEMM.
// ---------------------------------------------------------------------------
#define OK_WH 0
#define OK_YH 34816
#define OUT_SMEM 69632

__global__ __launch_bounds__(256, 1) void out_kernel(
    const float* __restrict__ x,
    const float* __restrict__ wo, const float* __restrict__ bo,
    const float* __restrict__ gamma, const float* __restrict__ beta,
    const float* __restrict__ mean, const float* __restrict__ var,
    float* __restrict__ out)
{
    extern __shared__ __align__(128) char smem[];
    const uint32_t sb = smem_u32(smem);
    const int tid = threadIdx.x;
    const int wid = tid >> 5, lane = tid & 31;
    const int b = blockIdx.z, c0 = blockIdx.y * 128, n0 = blockIdx.x * 128;

#pragma unroll
    for (int r = 0; r < 4; r++) {
        int idx = tid + r * 256;
        int row = idx >> 3, ch = idx & 7;
        const size_t g = ((size_t)b * N_ + n0 + row) * O_ + ch * 16;
        uint32_t off = (uint32_t)row * PITCH + ch * 32;
        CP16(sb + OK_YH + off,      d_y16 + g);
        CP16(sb + OK_YH + off + 16, d_y16 + g + 8);
    }
    CP_COMMIT();

#pragma unroll
    for (int r = 0; r < 16; r++) {
        int idx = tid + r * 256;
        int c = idx >> 5, ov = (idx & 31) << 2;
        float4 w = *(const float4*)(wo + (size_t)(c0 + c) * O_ + ov);
        uint32_t off = (uint32_t)c * PITCH + ov * 2;
        *(uint32_t*)(smem + OK_WH + off)     = h2pair(w.x, w.y);
        *(uint32_t*)(smem + OK_WH + off + 4) = h2pair(w.z, w.w);
    }
    CP_WAIT0();
    __syncthreads();

    float acc[16][4];
#pragma unroll
    for (int t = 0; t < 16; t++)
#pragma unroll
        for (int i = 0; i < 4; i++) acc[t][i] = 0.f;

    const uint32_t wa  = sb + OK_WH + (uint32_t)(wid * 16 + (lane & 15)) * PITCH + ((lane >> 4) & 1) * 16;
    const uint32_t yb4 = sb + OK_YH + (lane & 7) * PITCH + ((lane >> 3) & 1) * 16
                       + (lane >> 4) * (8 * PITCH);

#pragma unroll
    for (int s = 0; s < 8; s++) {
        uint32_t ahf[4];
        LDSM4(ahf[0], ahf[1], ahf[2], ahf[3], wa + s * 32);
#pragma unroll
        for (int jb2 = 0; jb2 < 8; jb2++) {
            uint32_t y0, y1, y2, y3;
            LDSM4(y0, y1, y2, y3, yb4 + jb2 * (16 * PITCH) + s * 32);
            MMAF16(acc[2 * jb2],     ahf, y0, y1);
            MMAF16(acc[2 * jb2 + 1], ahf, y2, y3);
        }
    }

    const int cr0 = c0 + wid * 16 + (lane >> 2);
#pragma unroll
    for (int h = 0; h < 2; h++) {
        const int c = cr0 + h * 8;
        const float inv = gamma[c] * rsqrtf(var[c] + 1e-5f);
        const float sh = beta[c] - mean[c] * inv + bo[c] * inv;
        const size_t rb = ((size_t)(b * C_ + c)) * N_ + n0 + 2 * (lane & 3);
#pragma unroll
        for (int jb = 0; jb < 16; jb++) {
            float2 xv = *(const float2*)(x + rb + jb * 8);
            float2 ov;
            ov.x = xv.x + acc[jb][2 * h + 0] * inv + sh;
            ov.y = xv.y + acc[jb][2 * h + 1] * inv + sh;
            *(float2*)(out + rb + jb * 8) = ov;
        }
    }
}

// ---------------------------------------------------------------------------
extern "C" void kernel_launch(void* const* d_in, const int* in_sizes, int n_in,
                              void* d_out, int out_size)
{
    const float* x     = (const float*)d_in[0];
    const float* wt    = (const float*)d_in[1];
    const float* bt    = (const float*)d_in[2];
    const float* wp    = (const float*)d_in[3];
    const float* bp    = (const float*)d_in[4];
    const float* wg    = (const float*)d_in[5];
    const float* bg    = (const float*)d_in[6];
    const float* wo    = (const float*)d_in[7];
    const float* bo    = (const float*)d_in[8];
    const float* gamma = (const float*)d_in[9];
    const float* beta  = (const float*)d_in[10];
    const float* mean  = (const float*)d_in[11];
    const float* var   = (const float*)d_in[12];
    float* out = (float*)d_out;

    cudaFuncSetAttribute(proj_kernel, cudaFuncAttributeMaxDynamicSharedMemorySize, PROJ_SMEM);
    cudaFuncSetAttribute(attn_kernel, cudaFuncAttributeMaxDynamicSharedMemorySize, ATTN_SMEM);
    cudaFuncSetAttribute(out_kernel,  cudaFuncAttributeMaxDynamicSharedMemorySize, OUT_SMEM);

    setup_kernel<<<3, 256>>>(wt, wp, wg);
    proj_kernel<<<dim3(32, 8, 3), 256, PROJ_SMEM>>>(x, bt, bp, bg);
    attn_kernel<<<dim3(16, 8), 256, ATTN_SMEM>>>();
    out_kernel<<<dim3(32, 2, 8), 256, OUT_SMEM>>>(x, wo, bo, gamma, beta, mean, var, out);
}

// round 13
// speedup vs baseline: 1.1971x; 1.1971x over previous
#include <cuda_runtime.h>
#include <cuda_fp16.h>
#include <cstdint>
#include <math.h>

#define B_ 8
#define C_ 256
#define N_ 4096
#define O_ 128

// Scratch (__device__ globals: allocation-free rule).
__device__ __half d_th [(size_t)B_ * N_ * O_];   // theta * log2(e), fp16
__device__ __half d_ph [(size_t)B_ * N_ * O_];
__device__ __half d_g  [(size_t)B_ * N_ * O_];
__device__ __half d_y16[(size_t)B_ * N_ * O_];
__device__ __half d_w16[3 * O_ * C_];

__device__ __forceinline__ uint32_t smem_u32(const void* p) {
    uint32_t a;
    asm("{ .reg .u64 t; cvta.to.shared.u64 t, %1; cvt.u32.u64 %0, t; }" : "=r"(a) : "l"(p));
    return a;
}

#define MMAF16(c, a, b0v, b1v) asm volatile( \
    "mma.sync.aligned.m16n8k16.row.col.f32.f16.f16.f32 " \
    "{%0,%1,%2,%3}, {%4,%5,%6,%7}, {%8,%9}, {%0,%1,%2,%3};" \
    : "+f"((c)[0]), "+f"((c)[1]), "+f"((c)[2]), "+f"((c)[3]) \
    : "r"((a)[0]), "r"((a)[1]), "r"((a)[2]), "r"((a)[3]), "r"(b0v), "r"(b1v))

// fp16-accumulator MMA (C/D are 2 x fp16x2 regs)
#define MMAH(c, a, b0v, b1v) asm volatile( \
    "mma.sync.aligned.m16n8k16.row.col.f16.f16.f16.f16 " \
    "{%0,%1}, {%2,%3,%4,%5}, {%6,%7}, {%0,%1};" \
    : "+r"((c)[0]), "+r"((c)[1]) \
    : "r"((a)[0]), "r"((a)[1]), "r"((a)[2]), "r"((a)[3]), "r"(b0v), "r"(b1v))

#define LDSM4(r0, r1, r2, r3, addr)  asm volatile("ldmatrix.sync.aligned.m8n8.x4.shared.b16 {%0,%1,%2,%3}, [%4];" : "=r"(r0), "=r"(r1), "=r"(r2), "=r"(r3) : "r"(addr))
#define LDSM4T(r0, r1, r2, r3, addr) asm volatile("ldmatrix.sync.aligned.m8n8.x4.trans.shared.b16 {%0,%1,%2,%3}, [%4];" : "=r"(r0), "=r"(r1), "=r"(r2), "=r"(r3) : "r"(addr))
#define CP16(dst, src)   asm volatile("cp.async.cg.shared.global [%0], [%1], 16;" :: "r"(dst), "l"(src))
#define CP_COMMIT()      asm volatile("cp.async.commit_group;" ::: "memory")
#define CP_WAIT0()       asm volatile("cp.async.wait_group 0;" ::: "memory")
#define CP_WAIT1()       asm volatile("cp.async.wait_group 1;" ::: "memory")
#define EX2H2(r)         asm("ex2.approx.f16x2 %0, %0;" : "+r"(r))
#define HMUL2(d, s)      asm("mul.rn.f16x2 %0, %0, %1;" : "+r"(d) : "r"(s))

__device__ __forceinline__ uint32_t h2pair(float a, float b) {
    uint32_t r;
    asm("cvt.rn.f16x2.f32 %0, %1, %2;" : "=r"(r) : "f"(b), "f"(a));
    return r;
}

#define PITCH 272
#define LOG2E 1.4426950408889634f
#define ONESH2 0x3C003C00u

// ---------------------------------------------------------------------------
// Kernel 0: W -> fp16 once.
// ---------------------------------------------------------------------------
__global__ void setup_kernel(const float* __restrict__ wt,
                             const float* __restrict__ wp,
                             const float* __restrict__ wg)
{
    const int z = blockIdx.x;
    const float* W = (z == 0) ? wt : (z == 1) ? wp : wg;
    __half* out = d_w16 + (size_t)z * O_ * C_;
    for (int i = threadIdx.x; i < O_ * C_ / 4; i += blockDim.x) {
        float4 w = *(const float4*)(W + i * 4);
        *(uint32_t*)(out + i * 4)     = h2pair(w.x, w.y);
        *(uint32_t*)(out + i * 4 + 2) = h2pair(w.z, w.w);
    }
}

// ---------------------------------------------------------------------------
// Kernel 1: projections, single fp16 GEMM.  theta gets *LOG2E.
// grid (32 n, 8 b, 3 z), 256 thr.
// ---------------------------------------------------------------------------
#define PJ_WH 0
#define PJ_X  67584
#define PJ_XBUF 8704
#define PJ_PW 528
#define PROJ_SMEM 84992

__global__ __launch_bounds__(256, 1) void proj_kernel(
    const float* __restrict__ x,
    const float* __restrict__ bt, const float* __restrict__ bp,
    const float* __restrict__ bg)
{
    extern __shared__ __align__(128) char smem[];
    const uint32_t sb = smem_u32(smem);
    const int tid = threadIdx.x;
    const int wid = tid >> 5, lane = tid & 31;
    const int b = blockIdx.y, n0 = blockIdx.x * 128, z = blockIdx.z;
    const float* bias = (z == 0) ? bt : (z == 1) ? bp : bg;
    __half* outp = (z == 0) ? d_th : (z == 1) ? d_ph : d_g;
    const __half* Wg = d_w16 + (size_t)z * O_ * C_;
    const float osc = (z == 0) ? LOG2E : 1.f;

#pragma unroll
    for (int r = 0; r < 16; r++) {
        int idx = tid + r * 256;
        int o = idx >> 5, ch = idx & 31;
        CP16(sb + PJ_WH + (uint32_t)o * PJ_PW + ch * 16, Wg + (size_t)o * C_ + ch * 8);
    }
    CP_COMMIT();

    float4 xr[4];
    auto ldg_chunk = [&](int ck) {
#pragma unroll
        for (int r = 0; r < 4; r++) {
            int idx = tid + r * 256;
            int cc = idx >> 5, nv = (idx & 31) << 2;
            xr[r] = *(const float4*)(x + ((size_t)(b * C_ + ck * 32 + cc)) * N_ + n0 + nv);
        }
    };
    auto sts_chunk = [&](int buf) {
#pragma unroll
        for (int r = 0; r < 4; r++) {
            int idx = tid + r * 256;
            int cc = idx >> 5, nv = (idx & 31) << 2;
            float4 v = xr[r];
            uint32_t base = PJ_X + buf * PJ_XBUF + (uint32_t)cc * PITCH + nv * 2;
            *(uint32_t*)(smem + base)     = h2pair(v.x, v.y);
            *(uint32_t*)(smem + base + 4) = h2pair(v.z, v.w);
        }
    };

    ldg_chunk(0);
    CP_WAIT0();
    sts_chunk(0);
    __syncthreads();

    float acc[16][4];
#pragma unroll
    for (int t = 0; t < 16; t++)
#pragma unroll
        for (int i = 0; i < 4; i++) acc[t][i] = 0.f;

    const uint32_t xa_off = (uint32_t)((lane & 7) + ((lane >> 4) << 3)) * PITCH
                          + (uint32_t)(wid * 16 + (((lane >> 3) & 1) << 3)) * 2;
    const uint32_t wb4 = (uint32_t)(lane & 7) * PJ_PW + ((lane >> 3) & 1) * 16
                       + (uint32_t)(lane >> 4) * (8 * PJ_PW);

    for (int ck = 0; ck < 8; ck++) {
        const int buf = ck & 1;
        if (ck < 7) ldg_chunk(ck + 1);
        const uint32_t xb = sb + PJ_X + buf * PJ_XBUF + xa_off;
#pragma unroll
        for (int s = 0; s < 2; s++) {
            uint32_t ah[4];
            LDSM4T(ah[0], ah[1], ah[2], ah[3], xb + s * (16 * PITCH));
            const uint32_t wcol = sb + PJ_WH + wb4 + (uint32_t)(ck * 32 + s * 16) * 2;
#pragma unroll
            for (int jb2 = 0; jb2 < 8; jb2++) {
                uint32_t b0, b1, b2, b3;
                LDSM4(b0, b1, b2, b3, wcol + jb2 * (16 * PJ_PW));
                MMAF16(acc[2 * jb2],     ah, b0, b1);
                MMAF16(acc[2 * jb2 + 1], ah, b2, b3);
            }
        }
        if (ck < 7) sts_chunk(buf ^ 1);
        __syncthreads();
    }

    const size_t row0 = (size_t)b * N_ + n0 + wid * 16 + (lane >> 2);
#pragma unroll
    for (int jb = 0; jb < 16; jb++) {
        const int o = jb * 8 + 2 * (lane & 3);
        float2 b2 = *(const float2*)(bias + o);
        *(uint32_t*)(outp + row0 * O_ + o)       = h2pair((acc[jb][0] + b2.x) * osc, (acc[jb][1] + b2.y) * osc);
        *(uint32_t*)(outp + (row0 + 8) * O_ + o) = h2pair((acc[jb][2] + b2.x) * osc, (acc[jb][3] + b2.y) * osc);
    }
}

// ---------------------------------------------------------------------------
// Kernel 2: fp16 flash attention, BM=256, BK=64, 8 warps x 32 q-rows.
// R10 structure; K and V triple-buffered so only ONE barrier per tile is
// needed (fast warps write slot (j+1)%3 while laggards read (j-1)%3).
// QK fp32-acc; softmax base-2 (ex2.f16x2); l via ones-MMA; PV fp16-acc.
// grid (16 q-tiles, 8 b), 256 threads.
// ---------------------------------------------------------------------------
#define BKA 64
#define NTA (N_ / BKA)
#define KBUF   17408
#define AK_OFF 0
#define AV_OFF (3 * KBUF)
#define ATTN_SMEM (6 * KBUF)

__global__ __launch_bounds__(256, 1) void attn_kernel()
{
    extern __shared__ __align__(128) char smem[];
    const uint32_t sb = smem_u32(smem);
    const int tid = threadIdx.x;
    const int wid = tid >> 5, lane = tid & 31;
    const int b = blockIdx.y, q0 = blockIdx.x * 256;

    // Q fragments: 2 M-blocks x 8 k-steps (theta already *log2e)
    uint32_t qh[2][8][4];
#pragma unroll
    for (int mb = 0; mb < 2; mb++) {
        const __half* Th = d_th + ((size_t)b * N_ + q0 + wid * 32 + mb * 16 + (lane >> 2)) * O_;
        const int c0 = 2 * (lane & 3);
#pragma unroll
        for (int s = 0; s < 8; s++) {
            qh[mb][s][0] = *(const uint32_t*)(Th + s * 16 + c0);
            qh[mb][s][1] = *(const uint32_t*)(Th + 8 * O_ + s * 16 + c0);
            qh[mb][s][2] = *(const uint32_t*)(Th + s * 16 + c0 + 8);
            qh[mb][s][3] = *(const uint32_t*)(Th + 8 * O_ + s * 16 + c0 + 8);
        }
    }

    const __half* Ph = d_ph + (size_t)b * N_ * O_;
    const __half* Vh = d_g  + (size_t)b * N_ * O_;

    const uint32_t kb4 = sb + AK_OFF + (lane & 7) * PITCH + ((lane >> 3) & 1) * 16
                       + (lane >> 4) * (8 * PITCH);
    const uint32_t vb4 = sb + AV_OFF + (lane & 7) * PITCH + ((lane >> 3) & 1) * (8 * PITCH)
                       + (lane >> 4) * 16;

    uint32_t acc2[2][16][2];   // fp16x2 accumulators
#pragma unroll
    for (int mb = 0; mb < 2; mb++)
#pragma unroll
        for (int k = 0; k < 16; k++) { acc2[mb][k][0] = 0u; acc2[mb][k][1] = 0u; }
    float lacc[2][4];
#pragma unroll
    for (int mb = 0; mb < 2; mb++)
#pragma unroll
        for (int i = 0; i < 4; i++) lacc[mb][i] = 0.f;
    float m0[2] = {-1e30f, -1e30f}, m1[2] = {-1e30f, -1e30f};

    auto load_tile = [&](int jt) {
        const size_t k0 = (size_t)jt * BKA;
        const uint32_t slot = (uint32_t)(jt % 3) * KBUF;
#pragma unroll
        for (int r = 0; r < 4; r++) {
            int idx = tid + r * 256;
            int k = idx >> 4, ch = idx & 15;
            uint32_t off = slot + (uint32_t)k * PITCH + ch * 16;
            const size_t g = (k0 + k) * O_ + ch * 8;
            CP16(sb + AK_OFF + off, Ph + g);
            CP16(sb + AV_OFF + off, Vh + g);
        }
    };

    load_tile(0);
    CP_COMMIT();

    for (int j = 0; j < NTA; j++) {
        const uint32_t slot = (uint32_t)(j % 3) * KBUF;
        if (j + 1 < NTA) { load_tile(j + 1); CP_COMMIT(); CP_WAIT1(); }
        else            { CP_WAIT0(); }
        __syncthreads();

        // S = Q K^T, fp32 acc (base-2 logits).  S[mb*8+nb]
        float S[16][4];
#pragma unroll
        for (int i = 0; i < 16; i++)
#pragma unroll
            for (int q = 0; q < 4; q++) S[i][q] = 0.f;
        const uint32_t kb = kb4 + slot;
#pragma unroll
        for (int s = 0; s < 8; s++) {
#pragma unroll
            for (int jb2 = 0; jb2 < 4; jb2++) {
                uint32_t b0, b1, b2, b3;
                LDSM4(b0, b1, b2, b3, kb + jb2 * (16 * PITCH) + s * 32);
                MMAF16(S[2 * jb2],         qh[0][s], b0, b1);
                MMAF16(S[2 * jb2 + 1],     qh[0][s], b2, b3);
                MMAF16(S[8 + 2 * jb2],     qh[1][s], b0, b1);
                MMAF16(S[8 + 2 * jb2 + 1], qh[1][s], b2, b3);
            }
        }

        // softmax (base 2), per M-block
        uint32_t ah[2][4][4];
#pragma unroll
        for (int mb = 0; mb < 2; mb++) {
            float mt0 = S[mb * 8][0], mt1 = S[mb * 8][2];
#pragma unroll
            for (int nb = 0; nb < 8; nb++) {
                mt0 = fmaxf(mt0, fmaxf(S[mb * 8 + nb][0], S[mb * 8 + nb][1]));
                mt1 = fmaxf(mt1, fmaxf(S[mb * 8 + nb][2], S[mb * 8 + nb][3]));
            }
            mt0 = fmaxf(mt0, __shfl_xor_sync(0xffffffffu, mt0, 1));
            mt0 = fmaxf(mt0, __shfl_xor_sync(0xffffffffu, mt0, 2));
            mt1 = fmaxf(mt1, __shfl_xor_sync(0xffffffffu, mt1, 1));
            mt1 = fmaxf(mt1, __shfl_xor_sync(0xffffffffu, mt1, 2));
            float mn0 = fmaxf(m0[mb], mt0), mn1 = fmaxf(m1[mb], mt1);
            float sc0 = exp2f(m0[mb] - mn0), sc1 = exp2f(m1[mb] - mn1);
            m0[mb] = mn0; m1[mb] = mn1;
            uint32_t scp0 = h2pair(sc0, sc0), scp1 = h2pair(sc1, sc1);
#pragma unroll
            for (int k = 0; k < 16; k++) {
                HMUL2(acc2[mb][k][0], scp0);
                HMUL2(acc2[mb][k][1], scp1);
            }
            lacc[mb][0] *= sc0; lacc[mb][1] *= sc0;
            lacc[mb][2] *= sc1; lacc[mb][3] *= sc1;
#pragma unroll
            for (int nb = 0; nb < 8; nb++) {
                const int i = mb * 8 + nb;
                uint32_t p0 = h2pair(S[i][0] - mn0, S[i][1] - mn0);
                uint32_t p1 = h2pair(S[i][2] - mn1, S[i][3] - mn1);
                EX2H2(p0);
                EX2H2(p1);
                ah[mb][nb >> 1][(nb & 1) * 2]     = p0;
                ah[mb][nb >> 1][(nb & 1) * 2 + 1] = p1;
            }
        }

        // PV (fp16 acc) + row sums via ones-MMA (fp32 acc)
        const uint32_t vb = vb4 + slot;
#pragma unroll
        for (int s2 = 0; s2 < 4; s2++) {
            MMAF16(lacc[0], ah[0][s2], ONESH2, ONESH2);
            MMAF16(lacc[1], ah[1][s2], ONESH2, ONESH2);
#pragma unroll
            for (int t2 = 0; t2 < 8; t2++) {
                uint32_t v0, v1, v2, v3;
                LDSM4T(v0, v1, v2, v3, vb + s2 * (16 * PITCH) + t2 * 32);
                MMAH(acc2[0][2 * t2],     ah[0][s2], v0, v1);
                MMAH(acc2[0][2 * t2 + 1], ah[0][s2], v2, v3);
                MMAH(acc2[1][2 * t2],     ah[1][s2], v0, v1);
                MMAH(acc2[1][2 * t2 + 1], ah[1][s2], v2, v3);
            }
        }
        // no bottom barrier: triple-buffered slots make the next iteration's
        // cp.async target disjoint from any slot still being read.
    }

    // epilogue: normalize by l (from ones-MMA), store y fp16
#pragma unroll
    for (int mb = 0; mb < 2; mb++) {
        const float inv0 = 1.f / lacc[mb][0];
        const float inv1 = 1.f / lacc[mb][2];
        const size_t row = (size_t)b * N_ + q0 + wid * 32 + mb * 16 + (lane >> 2);
#pragma unroll
        for (int k = 0; k < 16; k++) {
            const int col = (k >> 1) * 16 + (k & 1) * 8 + 2 * (lane & 3);
            __half2 h0 = *(__half2*)&acc2[mb][k][0];
            __half2 h1 = *(__half2*)&acc2[mb][k][1];
            *(uint32_t*)(d_y16 + row * O_ + col) =
                h2pair(__low2float(h0) * inv0, __high2float(h0) * inv0);
            *(uint32_t*)(d_y16 + (row + 8) * O_ + col) =
                h2pair(__low2float(h1) * inv1, __high2float(h1) * inv1);
        }
    }
}

// ---------------------------------------------------------------------------
// Kernel 3: out = x + BN(W_out y + b_out), single fp16 GEMM.
// Tile 64c x 128n, 128 threads, 2 CTAs/SM.  grid (32 n, 4 c, 8 b).
// ---------------------------------------------------------------------------
#define OK_WH 0
#define OK_YH 17408
#define OUT_SMEM 52224

__global__ __launch_bounds__(128, 2) void out_kernel(
    const float* __restrict__ x,
    const float* __restrict__ wo, const float* __restrict__ bo,
    const float* __restrict__ gamma, const float* __restrict__ beta,
    const float* __restrict__ mean, const float* __restrict__ var,
    float* __restrict__ out)
{
    extern __shared__ __align__(128) char smem[];
    const uint32_t sb = smem_u32(smem);
    const int tid = threadIdx.x;
    const int wid = tid >> 5, lane = tid & 31;
    const int b = blockIdx.z, c0 = blockIdx.y * 64, n0 = blockIdx.x * 128;

    // y fp16 via cp.async: 128 rows x 8 chunks of 32B = 1024 idx / 128 thr
#pragma unroll
    for (int r = 0; r < 8; r++) {
        int idx = tid + r * 128;
        int row = idx >> 3, ch = idx & 7;
        const size_t g = ((size_t)b * N_ + n0 + row) * O_ + ch * 16;
        uint32_t off = (uint32_t)row * PITCH + ch * 32;
        CP16(sb + OK_YH + off,      d_y16 + g);
        CP16(sb + OK_YH + off + 16, d_y16 + g + 8);
    }
    CP_COMMIT();

    // W_out tile (64 c x 128 o) fp32 -> fp16 smem: 2048 float4 / 128 thr
#pragma unroll
    for (int r = 0; r < 16; r++) {
        int idx = tid + r * 128;
        int c = idx >> 5, ov = (idx & 31) << 2;
        float4 w = *(const float4*)(wo + (size_t)(c0 + c) * O_ + ov);
        uint32_t off = (uint32_t)c * PITCH + ov * 2;
        *(uint32_t*)(smem + OK_WH + off)     = h2pair(w.x, w.y);
        *(uint32_t*)(smem + OK_WH + off + 4) = h2pair(w.z, w.w);
    }
    CP_WAIT0();
    __syncthreads();

    float acc[16][4];
#pragma unroll
    for (int t = 0; t < 16; t++)
#pragma unroll
        for (int i = 0; i < 4; i++) acc[t][i] = 0.f;

    const uint32_t wa  = sb + OK_WH + (uint32_t)(wid * 16 + (lane & 15)) * PITCH + ((lane >> 4) & 1) * 16;
    const uint32_t yb4 = sb + OK_YH + (lane & 7) * PITCH + ((lane >> 3) & 1) * 16
                       + (lane >> 4) * (8 * PITCH);

#pragma unroll
    for (int s = 0; s < 8; s++) {
        uint32_t ahf[4];
        LDSM4(ahf[0], ahf[1], ahf[2], ahf[3], wa + s * 32);
#pragma unroll
        for (int jb2 = 0; jb2 < 8; jb2++) {
            uint32_t y0, y1, y2, y3;
            LDSM4(y0, y1, y2, y3, yb4 + jb2 * (16 * PITCH) + s * 32);
            MMAF16(acc[2 * jb2],     ahf, y0, y1);
            MMAF16(acc[2 * jb2 + 1], ahf, y2, y3);
        }
    }

    const int cr0 = c0 + wid * 16 + (lane >> 2);
#pragma unroll
    for (int h = 0; h < 2; h++) {
        const int c = cr0 + h * 8;
        const float inv = gamma[c] * rsqrtf(var[c] + 1e-5f);
        const float sh = beta[c] - mean[c] * inv + bo[c] * inv;
        const size_t rb = ((size_t)(b * C_ + c)) * N_ + n0 + 2 * (lane & 3);
#pragma unroll
        for (int jb = 0; jb < 16; jb++) {
            float2 xv = *(const float2*)(x + rb + jb * 8);
            float2 ov;
            ov.x = xv.x + acc[jb][2 * h + 0] * inv + sh;
            ov.y = xv.y + acc[jb][2 * h + 1] * inv + sh;
            *(float2*)(out + rb + jb * 8) = ov;
        }
    }
}

// ---------------------------------------------------------------------------
extern "C" void kernel_launch(void* const* d_in, const int* in_sizes, int n_in,
                              void* d_out, int out_size)
{
    const float* x     = (const float*)d_in[0];
    const float* wt    = (const float*)d_in[1];
    const float* bt    = (const float*)d_in[2];
    const float* wp    = (const float*)d_in[3];
    const float* bp    = (const float*)d_in[4];
    const float* wg    = (const float*)d_in[5];
    const float* bg    = (const float*)d_in[6];
    const float* wo    = (const float*)d_in[7];
    const float* bo    = (const float*)d_in[8];
    const float* gamma = (const float*)d_in[9];
    const float* beta  = (const float*)d_in[10];
    const float* mean  = (const float*)d_in[11];
    const float* var   = (const float*)d_in[12];
    float* out = (float*)d_out;

    cudaFuncSetAttribute(proj_kernel, cudaFuncAttributeMaxDynamicSharedMemorySize, PROJ_SMEM);
    cudaFuncSetAttribute(attn_kernel, cudaFuncAttributeMaxDynamicSharedMemorySize, ATTN_SMEM);
    cudaFuncSetAttribute(out_kernel,  cudaFuncAttributeMaxDynamicSharedMemorySize, OUT_SMEM);

    setup_kernel<<<3, 256>>>(wt, wp, wg);
    proj_kernel<<<dim3(32, 8, 3), 256, PROJ_SMEM>>>(x, bt, bp, bg);
    attn_kernel<<<dim3(16, 8), 256, ATTN_SMEM>>>();
    out_kernel<<<dim3(32, 4, 8), 128, OUT_SMEM>>>(x, wo, bo, gamma, beta, mean, var, out);
}

// round 14
// speedup vs baseline: 1.2077x; 1.0089x over previous
#include <cuda_runtime.h>
#include <cuda_fp16.h>
#include <cstdint>
#include <math.h>

#define B_ 8
#define C_ 256
#define N_ 4096
#define O_ 128

// Scratch (__device__ globals: allocation-free rule).
__device__ __half d_th [(size_t)B_ * N_ * O_];   // theta * log2(e), fp16
__device__ __half d_ph [(size_t)B_ * N_ * O_];
__device__ __half d_g  [(size_t)B_ * N_ * O_];
__device__ __half d_y16[(size_t)B_ * N_ * O_];
__device__ __half d_w16[3 * O_ * C_];

__device__ __forceinline__ uint32_t smem_u32(const void* p) {
    uint32_t a;
    asm("{ .reg .u64 t; cvta.to.shared.u64 t, %1; cvt.u32.u64 %0, t; }" : "=r"(a) : "l"(p));
    return a;
}

#define MMAF16(c, a, b0v, b1v) asm volatile( \
    "mma.sync.aligned.m16n8k16.row.col.f32.f16.f16.f32 " \
    "{%0,%1,%2,%3}, {%4,%5,%6,%7}, {%8,%9}, {%0,%1,%2,%3};" \
    : "+f"((c)[0]), "+f"((c)[1]), "+f"((c)[2]), "+f"((c)[3]) \
    : "r"((a)[0]), "r"((a)[1]), "r"((a)[2]), "r"((a)[3]), "r"(b0v), "r"(b1v))

// fp16-accumulator MMA (C/D are 2 x fp16x2 regs)
#define MMAH(c, a, b0v, b1v) asm volatile( \
    "mma.sync.aligned.m16n8k16.row.col.f16.f16.f16.f16 " \
    "{%0,%1}, {%2,%3,%4,%5}, {%6,%7}, {%0,%1};" \
    : "+r"((c)[0]), "+r"((c)[1]) \
    : "r"((a)[0]), "r"((a)[1]), "r"((a)[2]), "r"((a)[3]), "r"(b0v), "r"(b1v))

#define LDSM4(r0, r1, r2, r3, addr)  asm volatile("ldmatrix.sync.aligned.m8n8.x4.shared.b16 {%0,%1,%2,%3}, [%4];" : "=r"(r0), "=r"(r1), "=r"(r2), "=r"(r3) : "r"(addr))
#define LDSM4T(r0, r1, r2, r3, addr) asm volatile("ldmatrix.sync.aligned.m8n8.x4.trans.shared.b16 {%0,%1,%2,%3}, [%4];" : "=r"(r0), "=r"(r1), "=r"(r2), "=r"(r3) : "r"(addr))
#define CP16(dst, src)   asm volatile("cp.async.cg.shared.global [%0], [%1], 16;" :: "r"(dst), "l"(src))
#define CP_COMMIT()      asm volatile("cp.async.commit_group;" ::: "memory")
#define CP_WAIT0()       asm volatile("cp.async.wait_group 0;" ::: "memory")
#define CP_WAIT1()       asm volatile("cp.async.wait_group 1;" ::: "memory")
#define EX2H2(r)         asm("ex2.approx.f16x2 %0, %0;" : "+r"(r))
#define HMUL2(d, s)      asm("mul.rn.f16x2 %0, %0, %1;" : "+r"(d) : "r"(s))

__device__ __forceinline__ uint32_t h2pair(float a, float b) {
    uint32_t r;
    asm("cvt.rn.f16x2.f32 %0, %1, %2;" : "=r"(r) : "f"(b), "f"(a));
    return r;
}

#define PITCH 272
#define LOG2E 1.4426950408889634f
#define ONESH2 0x3C003C00u

// ---------------------------------------------------------------------------
// Kernel 0: W -> fp16 once.
// ---------------------------------------------------------------------------
__global__ void setup_kernel(const float* __restrict__ wt,
                             const float* __restrict__ wp,
                             const float* __restrict__ wg)
{
    const int z = blockIdx.x;
    const float* W = (z == 0) ? wt : (z == 1) ? wp : wg;
    __half* out = d_w16 + (size_t)z * O_ * C_;
    for (int i = threadIdx.x; i < O_ * C_ / 4; i += blockDim.x) {
        float4 w = *(const float4*)(W + i * 4);
        *(uint32_t*)(out + i * 4)     = h2pair(w.x, w.y);
        *(uint32_t*)(out + i * 4 + 2) = h2pair(w.z, w.w);
    }
}

// ---------------------------------------------------------------------------
// Kernel 1: FUSED projections.  One block per (n-tile, b); x tile loaded and
// converted ONCE; loop z=0..2 with double-buffered W (load overlaps compute).
// out[n][o] = sum_c W[o][c] x[c][n] + bias.  theta scaled by LOG2E.
// grid (32 n, 8 b), 256 thr.
// ---------------------------------------------------------------------------
#define PJ_X   0
#define PJ_W   69632
#define PJ_WBUF 67584
#define PJ_PW  528
#define PROJ_SMEM (69632 + 2 * 67584)

__global__ __launch_bounds__(256, 1) void proj_kernel(
    const float* __restrict__ x,
    const float* __restrict__ bt, const float* __restrict__ bp,
    const float* __restrict__ bg)
{
    extern __shared__ __align__(128) char smem[];
    const uint32_t sb = smem_u32(smem);
    const int tid = threadIdx.x;
    const int wid = tid >> 5, lane = tid & 31;
    const int b = blockIdx.y, n0 = blockIdx.x * 128;

    auto load_w = [&](int z, int buf) {
        const __half* Wg = d_w16 + (size_t)z * O_ * C_;
        const uint32_t base = PJ_W + (uint32_t)buf * PJ_WBUF;
#pragma unroll
        for (int r = 0; r < 16; r++) {
            int idx = tid + r * 256;
            int o = idx >> 5, ch = idx & 31;
            CP16(sb + base + (uint32_t)o * PJ_PW + ch * 16, Wg + (size_t)o * C_ + ch * 8);
        }
        CP_COMMIT();
    };

    load_w(0, 0);

    // x tile [256 c x 128 n] fp32 -> fp16 smem (persistent), pipelined ldg/sts
    {
        float4 xr[2][4];
        auto ldg_chunk = [&](int ck, float4 (&xr_)[4]) {
#pragma unroll
            for (int r = 0; r < 4; r++) {
                int idx = tid + r * 256;
                int cc = idx >> 5, nv = (idx & 31) << 2;
                xr_[r] = *(const float4*)(x + ((size_t)(b * C_ + ck * 32 + cc)) * N_ + n0 + nv);
            }
        };
        auto sts_chunk = [&](int ck, float4 (&xr_)[4]) {
#pragma unroll
            for (int r = 0; r < 4; r++) {
                int idx = tid + r * 256;
                int cc = idx >> 5, nv = (idx & 31) << 2;
                float4 v = xr_[r];
                uint32_t base = PJ_X + (uint32_t)(ck * 32 + cc) * PITCH + nv * 2;
                *(uint32_t*)(smem + base)     = h2pair(v.x, v.y);
                *(uint32_t*)(smem + base + 4) = h2pair(v.z, v.w);
            }
        };
        ldg_chunk(0, xr[0]);
#pragma unroll
        for (int ck = 0; ck < 8; ck++) {
            if (ck < 7) ldg_chunk(ck + 1, xr[(ck + 1) & 1]);
            sts_chunk(ck, xr[ck & 1]);
        }
    }
    CP_WAIT0();
    __syncthreads();
    load_w(1, 1);   // overlaps z=0 compute

    const uint32_t xa_off = (uint32_t)((lane & 7) + ((lane >> 4) << 3)) * PITCH
                          + (uint32_t)(wid * 16 + (((lane >> 3) & 1) << 3)) * 2;
    const uint32_t wb4 = (uint32_t)(lane & 7) * PJ_PW + ((lane >> 3) & 1) * 16
                       + (uint32_t)(lane >> 4) * (8 * PJ_PW);
    const size_t row0 = (size_t)b * N_ + n0 + wid * 16 + (lane >> 2);

#pragma unroll
    for (int z = 0; z < 3; z++) {
        const float* bias = (z == 0) ? bt : (z == 1) ? bp : bg;
        __half* outp = (z == 0) ? d_th : (z == 1) ? d_ph : d_g;
        const float osc = (z == 0) ? LOG2E : 1.f;
        const uint32_t wbase = sb + PJ_W + (uint32_t)(z & 1) * PJ_WBUF + wb4;

        float acc[16][4];
#pragma unroll
        for (int t = 0; t < 16; t++)
#pragma unroll
            for (int i = 0; i < 4; i++) acc[t][i] = 0.f;

#pragma unroll
        for (int ck = 0; ck < 8; ck++) {
            const uint32_t xb = sb + PJ_X + (uint32_t)ck * (32 * PITCH) + xa_off;
#pragma unroll
            for (int s = 0; s < 2; s++) {
                uint32_t ah[4];
                LDSM4T(ah[0], ah[1], ah[2], ah[3], xb + s * (16 * PITCH));
                const uint32_t wcol = wbase + (uint32_t)(ck * 32 + s * 16) * 2;
#pragma unroll
                for (int jb2 = 0; jb2 < 8; jb2++) {
                    uint32_t b0, b1, b2, b3;
                    LDSM4(b0, b1, b2, b3, wcol + jb2 * (16 * PJ_PW));
                    MMAF16(acc[2 * jb2],     ah, b0, b1);
                    MMAF16(acc[2 * jb2 + 1], ah, b2, b3);
                }
            }
        }

#pragma unroll
        for (int jb = 0; jb < 16; jb++) {
            const int o = jb * 8 + 2 * (lane & 3);
            float2 b2 = *(const float2*)(bias + o);
            *(uint32_t*)(outp + row0 * O_ + o)       = h2pair((acc[jb][0] + b2.x) * osc, (acc[jb][1] + b2.y) * osc);
            *(uint32_t*)(outp + (row0 + 8) * O_ + o) = h2pair((acc[jb][2] + b2.x) * osc, (acc[jb][3] + b2.y) * osc);
        }

        if (z < 2) {
            CP_WAIT0();          // W(z+1) landed
            __syncthreads();     // all warps done reading W(z) buffer
            if (z == 0) load_w(2, 0);   // overlaps z=1 compute
        }
    }
}

// ---------------------------------------------------------------------------
// Kernel 2: fp16 flash attention, BM=256, BK=64, 8 warps x 32 q-rows.
// Triple-buffered K/V (one barrier per tile).  Warp-vote skips the acc
// rescale when the running max is unchanged (exact no-op elimination).
// QK fp32-acc; softmax base-2 (ex2.f16x2); l via ones-MMA; PV fp16-acc.
// grid (16 q-tiles, 8 b), 256 threads.
// ---------------------------------------------------------------------------
#define BKA 64
#define NTA (N_ / BKA)
#define KBUF   17408
#define AK_OFF 0
#define AV_OFF (3 * KBUF)
#define ATTN_SMEM (6 * KBUF)

__global__ __launch_bounds__(256, 1) void attn_kernel()
{
    extern __shared__ __align__(128) char smem[];
    const uint32_t sb = smem_u32(smem);
    const int tid = threadIdx.x;
    const int wid = tid >> 5, lane = tid & 31;
    const int b = blockIdx.y, q0 = blockIdx.x * 256;

    // Q fragments: 2 M-blocks x 8 k-steps (theta already *log2e)
    uint32_t qh[2][8][4];
#pragma unroll
    for (int mb = 0; mb < 2; mb++) {
        const __half* Th = d_th + ((size_t)b * N_ + q0 + wid * 32 + mb * 16 + (lane >> 2)) * O_;
        const int c0 = 2 * (lane & 3);
#pragma unroll
        for (int s = 0; s < 8; s++) {
            qh[mb][s][0] = *(const uint32_t*)(Th + s * 16 + c0);
            qh[mb][s][1] = *(const uint32_t*)(Th + 8 * O_ + s * 16 + c0);
            qh[mb][s][2] = *(const uint32_t*)(Th + s * 16 + c0 + 8);
            qh[mb][s][3] = *(const uint32_t*)(Th + 8 * O_ + s * 16 + c0 + 8);
        }
    }

    const __half* Ph = d_ph + (size_t)b * N_ * O_;
    const __half* Vh = d_g  + (size_t)b * N_ * O_;

    const uint32_t kb4 = sb + AK_OFF + (lane & 7) * PITCH + ((lane >> 3) & 1) * 16
                       + (lane >> 4) * (8 * PITCH);
    const uint32_t vb4 = sb + AV_OFF + (lane & 7) * PITCH + ((lane >> 3) & 1) * (8 * PITCH)
                       + (lane >> 4) * 16;

    uint32_t acc2[2][16][2];   // fp16x2 accumulators
#pragma unroll
    for (int mb = 0; mb < 2; mb++)
#pragma unroll
        for (int k = 0; k < 16; k++) { acc2[mb][k][0] = 0u; acc2[mb][k][1] = 0u; }
    float lacc[2][4];
#pragma unroll
    for (int mb = 0; mb < 2; mb++)
#pragma unroll
        for (int i = 0; i < 4; i++) lacc[mb][i] = 0.f;
    float m0[2] = {-1e30f, -1e30f}, m1[2] = {-1e30f, -1e30f};

    auto load_tile = [&](int jt) {
        const size_t k0 = (size_t)jt * BKA;
        const uint32_t slot = (uint32_t)(jt % 3) * KBUF;
#pragma unroll
        for (int r = 0; r < 4; r++) {
            int idx = tid + r * 256;
            int k = idx >> 4, ch = idx & 15;
            uint32_t off = slot + (uint32_t)k * PITCH + ch * 16;
            const size_t g = (k0 + k) * O_ + ch * 8;
            CP16(sb + AK_OFF + off, Ph + g);
            CP16(sb + AV_OFF + off, Vh + g);
        }
    };

    load_tile(0);
    CP_COMMIT();

    for (int j = 0; j < NTA; j++) {
        const uint32_t slot = (uint32_t)(j % 3) * KBUF;
        if (j + 1 < NTA) { load_tile(j + 1); CP_COMMIT(); CP_WAIT1(); }
        else            { CP_WAIT0(); }
        __syncthreads();

        // S = Q K^T, fp32 acc (base-2 logits).  S[mb*8+nb]
        float S[16][4];
#pragma unroll
        for (int i = 0; i < 16; i++)
#pragma unroll
            for (int q = 0; q < 4; q++) S[i][q] = 0.f;
        const uint32_t kb = kb4 + slot;
#pragma unroll
        for (int s = 0; s < 8; s++) {
#pragma unroll
            for (int jb2 = 0; jb2 < 4; jb2++) {
                uint32_t b0, b1, b2, b3;
                LDSM4(b0, b1, b2, b3, kb + jb2 * (16 * PITCH) + s * 32);
                MMAF16(S[2 * jb2],         qh[0][s], b0, b1);
                MMAF16(S[2 * jb2 + 1],     qh[0][s], b2, b3);
                MMAF16(S[8 + 2 * jb2],     qh[1][s], b0, b1);
                MMAF16(S[8 + 2 * jb2 + 1], qh[1][s], b2, b3);
            }
        }

        // softmax (base 2), per M-block; rescale skipped when max unchanged
        uint32_t ah[2][4][4];
#pragma unroll
        for (int mb = 0; mb < 2; mb++) {
            float mt0 = S[mb * 8][0], mt1 = S[mb * 8][2];
#pragma unroll
            for (int nb = 0; nb < 8; nb++) {
                mt0 = fmaxf(mt0, fmaxf(S[mb * 8 + nb][0], S[mb * 8 + nb][1]));
                mt1 = fmaxf(mt1, fmaxf(S[mb * 8 + nb][2], S[mb * 8 + nb][3]));
            }
            mt0 = fmaxf(mt0, __shfl_xor_sync(0xffffffffu, mt0, 1));
            mt0 = fmaxf(mt0, __shfl_xor_sync(0xffffffffu, mt0, 2));
            mt1 = fmaxf(mt1, __shfl_xor_sync(0xffffffffu, mt1, 1));
            mt1 = fmaxf(mt1, __shfl_xor_sync(0xffffffffu, mt1, 2));
            float mn0 = fmaxf(m0[mb], mt0), mn1 = fmaxf(m1[mb], mt1);
            float sc0 = exp2f(m0[mb] - mn0), sc1 = exp2f(m1[mb] - mn1);
            m0[mb] = mn0; m1[mb] = mn1;
            if (!__all_sync(0xffffffffu, (sc0 == 1.f) && (sc1 == 1.f))) {
                uint32_t scp0 = h2pair(sc0, sc0), scp1 = h2pair(sc1, sc1);
#pragma unroll
                for (int k = 0; k < 16; k++) {
                    HMUL2(acc2[mb][k][0], scp0);
                    HMUL2(acc2[mb][k][1], scp1);
                }
                lacc[mb][0] *= sc0; lacc[mb][1] *= sc0;
                lacc[mb][2] *= sc1; lacc[mb][3] *= sc1;
            }
#pragma unroll
            for (int nb = 0; nb < 8; nb++) {
                const int i = mb * 8 + nb;
                uint32_t p0 = h2pair(S[i][0] - mn0, S[i][1] - mn0);
                uint32_t p1 = h2pair(S[i][2] - mn1, S[i][3] - mn1);
                EX2H2(p0);
                EX2H2(p1);
                ah[mb][nb >> 1][(nb & 1) * 2]     = p0;
                ah[mb][nb >> 1][(nb & 1) * 2 + 1] = p1;
            }
        }

        // PV (fp16 acc) + row sums via ones-MMA (fp32 acc)
        const uint32_t vb = vb4 + slot;
#pragma unroll
        for (int s2 = 0; s2 < 4; s2++) {
            MMAF16(lacc[0], ah[0][s2], ONESH2, ONESH2);
            MMAF16(lacc[1], ah[1][s2], ONESH2, ONESH2);
#pragma unroll
            for (int t2 = 0; t2 < 8; t2++) {
                uint32_t v0, v1, v2, v3;
                LDSM4T(v0, v1, v2, v3, vb + s2 * (16 * PITCH) + t2 * 32);
                MMAH(acc2[0][2 * t2],     ah[0][s2], v0, v1);
                MMAH(acc2[0][2 * t2 + 1], ah[0][s2], v2, v3);
                MMAH(acc2[1][2 * t2],     ah[1][s2], v0, v1);
                MMAH(acc2[1][2 * t2 + 1], ah[1][s2], v2, v3);
            }
        }
        // no bottom barrier: triple-buffered slots keep writes disjoint.
    }

    // epilogue: normalize by l (from ones-MMA), store y fp16
#pragma unroll
    for (int mb = 0; mb < 2; mb++) {
        const float inv0 = 1.f / lacc[mb][0];
        const float inv1 = 1.f / lacc[mb][2];
        const size_t row = (size_t)b * N_ + q0 + wid * 32 + mb * 16 + (lane >> 2);
#pragma unroll
        for (int k = 0; k < 16; k++) {
            const int col = (k >> 1) * 16 + (k & 1) * 8 + 2 * (lane & 3);
            __half2 h0 = *(__half2*)&acc2[mb][k][0];
            __half2 h1 = *(__half2*)&acc2[mb][k][1];
            *(uint32_t*)(d_y16 + row * O_ + col) =
                h2pair(__low2float(h0) * inv0, __high2float(h0) * inv0);
            *(uint32_t*)(d_y16 + (row + 8) * O_ + col) =
                h2pair(__low2float(h1) * inv1, __high2float(h1) * inv1);
        }
    }
}

// ---------------------------------------------------------------------------
// Kernel 3: out = x + BN(W_out y + b_out), single fp16 GEMM.
// Tile 64c x 128n, 128 threads, 2 CTAs/SM.  grid (32 n, 4 c, 8 b).
// ---------------------------------------------------------------------------
#define OK_WH 0
#define OK_YH 17408
#define OUT_SMEM 52224

__global__ __launch_bounds__(128, 2) void out_kernel(
    const float* __restrict__ x,
    const float* __restrict__ wo, const float* __restrict__ bo,
    const float* __restrict__ gamma, const float* __restrict__ beta,
    const float* __restrict__ mean, const float* __restrict__ var,
    float* __restrict__ out)
{
    extern __shared__ __align__(128) char smem[];
    const uint32_t sb = smem_u32(smem);
    const int tid = threadIdx.x;
    const int wid = tid >> 5, lane = tid & 31;
    const int b = blockIdx.z, c0 = blockIdx.y * 64, n0 = blockIdx.x * 128;

#pragma unroll
    for (int r = 0; r < 8; r++) {
        int idx = tid + r * 128;
        int row = idx >> 3, ch = idx & 7;
        const size_t g = ((size_t)b * N_ + n0 + row) * O_ + ch * 16;
        uint32_t off = (uint32_t)row * PITCH + ch * 32;
        CP16(sb + OK_YH + off,      d_y16 + g);
        CP16(sb + OK_YH + off + 16, d_y16 + g + 8);
    }
    CP_COMMIT();

#pragma unroll
    for (int r = 0; r < 16; r++) {
        int idx = tid + r * 128;
        int c = idx >> 5, ov = (idx & 31) << 2;
        float4 w = *(const float4*)(wo + (size_t)(c0 + c) * O_ + ov);
        uint32_t off = (uint32_t)c * PITCH + ov * 2;
        *(uint32_t*)(smem + OK_WH + off)     = h2pair(w.x, w.y);
        *(uint32_t*)(smem + OK_WH + off + 4) = h2pair(w.z, w.w);
    }
    CP_WAIT0();
    __syncthreads();

    float acc[16][4];
#pragma unroll
    for (int t = 0; t < 16; t++)
#pragma unroll
        for (int i = 0; i < 4; i++) acc[t][i] = 0.f;

    const uint32_t wa  = sb + OK_WH + (uint32_t)(wid * 16 + (lane & 15)) * PITCH + ((lane >> 4) & 1) * 16;
    const uint32_t yb4 = sb + OK_YH + (lane & 7) * PITCH + ((lane >> 3) & 1) * 16
                       + (lane >> 4) * (8 * PITCH);

#pragma unroll
    for (int s = 0; s < 8; s++) {
        uint32_t ahf[4];
        LDSM4(ahf[0], ahf[1], ahf[2], ahf[3], wa + s * 32);
#pragma unroll
        for (int jb2 = 0; jb2 < 8; jb2++) {
            uint32_t y0, y1, y2, y3;
            LDSM4(y0, y1, y2, y3, yb4 + jb2 * (16 * PITCH) + s * 32);
            MMAF16(acc[2 * jb2],     ahf, y0, y1);
            MMAF16(acc[2 * jb2 + 1], ahf, y2, y3);
        }
    }

    const int cr0 = c0 + wid * 16 + (lane >> 2);
#pragma unroll
    for (int h = 0; h < 2; h++) {
        const int c = cr0 + h * 8;
        const float inv = gamma[c] * rsqrtf(var[c] + 1e-5f);
        const float sh = beta[c] - mean[c] * inv + bo[c] * inv;
        const size_t rb = ((size_t)(b * C_ + c)) * N_ + n0 + 2 * (lane & 3);
#pragma unroll
        for (int jb = 0; jb < 16; jb++) {
            float2 xv = *(const float2*)(x + rb + jb * 8);
            float2 ov;
            ov.x = xv.x + acc[jb][2 * h + 0] * inv + sh;
            ov.y = xv.y + acc[jb][2 * h + 1] * inv + sh;
            *(float2*)(out + rb + jb * 8) = ov;
        }
    }
}

// ---------------------------------------------------------------------------
extern "C" void kernel_launch(void* const* d_in, const int* in_sizes, int n_in,
                              void* d_out, int out_size)
{
    const float* x     = (const float*)d_in[0];
    const float* wt    = (const float*)d_in[1];
    const float* bt    = (const float*)d_in[2];
    const float* wp    = (const float*)d_in[3];
    const float* bp    = (const float*)d_in[4];
    const float* wg    = (const float*)d_in[5];
    const float* bg    = (const float*)d_in[6];
    const float* wo    = (const float*)d_in[7];
    const float* bo    = (const float*)d_in[8];
    const float* gamma = (const float*)d_in[9];
    const float* beta  = (const float*)d_in[10];
    const float* mean  = (const float*)d_in[11];
    const float* var   = (const float*)d_in[12];
    float* out = (float*)d_out;

    cudaFuncSetAttribute(proj_kernel, cudaFuncAttributeMaxDynamicSharedMemorySize, PROJ_SMEM);
    cudaFuncSetAttribute(attn_kernel, cudaFuncAttributeMaxDynamicSharedMemorySize, ATTN_SMEM);
    cudaFuncSetAttribute(out_kernel,  cudaFuncAttributeMaxDynamicSharedMemorySize, OUT_SMEM);

    setup_kernel<<<3, 256>>>(wt, wp, wg);
    proj_kernel<<<dim3(32, 8), 256, PROJ_SMEM>>>(x, bt, bp, bg);
    attn_kernel<<<dim3(16, 8), 256, ATTN_SMEM>>>();
    out_kernel<<<dim3(32, 4, 8), 128, OUT_SMEM>>>(x, wo, bo, gamma, beta, mean, var, out);
}

// round 15
// speedup vs baseline: 1.2239x; 1.0134x over previous
#include <cuda_runtime.h>
#include <cuda_fp16.h>
#include <cstdint>
#include <math.h>

#define B_ 8
#define C_ 256
#define N_ 4096
#define O_ 128

// Scratch (__device__ globals: allocation-free rule).
__device__ __half d_th [(size_t)B_ * N_ * O_];   // theta * log2(e), fp16
__device__ __half d_ph [(size_t)B_ * N_ * O_];
__device__ __half d_g  [(size_t)B_ * N_ * O_];
__device__ __half d_y16[(size_t)B_ * N_ * O_];
__device__ __half d_w16[3 * O_ * C_];

__device__ __forceinline__ uint32_t smem_u32(const void* p) {
    uint32_t a;
    asm("{ .reg .u64 t; cvta.to.shared.u64 t, %1; cvt.u32.u64 %0, t; }" : "=r"(a) : "l"(p));
    return a;
}

#define MMAF16(c, a, b0v, b1v) asm volatile( \
    "mma.sync.aligned.m16n8k16.row.col.f32.f16.f16.f32 " \
    "{%0,%1,%2,%3}, {%4,%5,%6,%7}, {%8,%9}, {%0,%1,%2,%3};" \
    : "+f"((c)[0]), "+f"((c)[1]), "+f"((c)[2]), "+f"((c)[3]) \
    : "r"((a)[0]), "r"((a)[1]), "r"((a)[2]), "r"((a)[3]), "r"(b0v), "r"(b1v))

// fp16-accumulator MMA (C/D are 2 x fp16x2 regs)
#define MMAH(c, a, b0v, b1v) asm volatile( \
    "mma.sync.aligned.m16n8k16.row.col.f16.f16.f16.f16 " \
    "{%0,%1}, {%2,%3,%4,%5}, {%6,%7}, {%0,%1};" \
    : "+r"((c)[0]), "+r"((c)[1]) \
    : "r"((a)[0]), "r"((a)[1]), "r"((a)[2]), "r"((a)[3]), "r"(b0v), "r"(b1v))

#define LDSM4(r0, r1, r2, r3, addr)  asm volatile("ldmatrix.sync.aligned.m8n8.x4.shared.b16 {%0,%1,%2,%3}, [%4];" : "=r"(r0), "=r"(r1), "=r"(r2), "=r"(r3) : "r"(addr))
#define LDSM4T(r0, r1, r2, r3, addr) asm volatile("ldmatrix.sync.aligned.m8n8.x4.trans.shared.b16 {%0,%1,%2,%3}, [%4];" : "=r"(r0), "=r"(r1), "=r"(r2), "=r"(r3) : "r"(addr))
#define CP16(dst, src)   asm volatile("cp.async.cg.shared.global [%0], [%1], 16;" :: "r"(dst), "l"(src))
#define CP_COMMIT()      asm volatile("cp.async.commit_group;" ::: "memory")
#define CP_WAIT0()       asm volatile("cp.async.wait_group 0;" ::: "memory")
#define CP_WAIT1()       asm volatile("cp.async.wait_group 1;" ::: "memory")
#define EX2H2(r)         asm("ex2.approx.f16x2 %0, %0;" : "+r"(r))
#define HMUL2(d, s)      asm("mul.rn.f16x2 %0, %0, %1;" : "+r"(d) : "r"(s))

__device__ __forceinline__ uint32_t h2pair(float a, float b) {
    uint32_t r;
    asm("cvt.rn.f16x2.f32 %0, %1, %2;" : "=r"(r) : "f"(b), "f"(a));
    return r;
}

#define PITCH 272
#define LOG2E 1.4426950408889634f
#define ONESH2 0x3C003C00u

// ---------------------------------------------------------------------------
// Kernel 0: W -> fp16 once.
// ---------------------------------------------------------------------------
__global__ void setup_kernel(const float* __restrict__ wt,
                             const float* __restrict__ wp,
                             const float* __restrict__ wg)
{
    const int z = blockIdx.x;
    const float* W = (z == 0) ? wt : (z == 1) ? wp : wg;
    __half* out = d_w16 + (size_t)z * O_ * C_;
    for (int i = threadIdx.x; i < O_ * C_ / 4; i += blockDim.x) {
        float4 w = *(const float4*)(W + i * 4);
        *(uint32_t*)(out + i * 4)     = h2pair(w.x, w.y);
        *(uint32_t*)(out + i * 4 + 2) = h2pair(w.z, w.w);
    }
}

// ---------------------------------------------------------------------------
// Kernel 1: FUSED projections (x tile loaded once, W double-buffered).
// grid (32 n, 8 b), 256 thr.
// ---------------------------------------------------------------------------
#define PJ_X   0
#define PJ_W   69632
#define PJ_WBUF 67584
#define PJ_PW  528
#define PROJ_SMEM (69632 + 2 * 67584)

__global__ __launch_bounds__(256, 1) void proj_kernel(
    const float* __restrict__ x,
    const float* __restrict__ bt, const float* __restrict__ bp,
    const float* __restrict__ bg)
{
    extern __shared__ __align__(128) char smem[];
    const uint32_t sb = smem_u32(smem);
    const int tid = threadIdx.x;
    const int wid = tid >> 5, lane = tid & 31;
    const int b = blockIdx.y, n0 = blockIdx.x * 128;

    auto load_w = [&](int z, int buf) {
        const __half* Wg = d_w16 + (size_t)z * O_ * C_;
        const uint32_t base = PJ_W + (uint32_t)buf * PJ_WBUF;
#pragma unroll
        for (int r = 0; r < 16; r++) {
            int idx = tid + r * 256;
            int o = idx >> 5, ch = idx & 31;
            CP16(sb + base + (uint32_t)o * PJ_PW + ch * 16, Wg + (size_t)o * C_ + ch * 8);
        }
        CP_COMMIT();
    };

    load_w(0, 0);

    {
        float4 xr[2][4];
        auto ldg_chunk = [&](int ck, float4 (&xr_)[4]) {
#pragma unroll
            for (int r = 0; r < 4; r++) {
                int idx = tid + r * 256;
                int cc = idx >> 5, nv = (idx & 31) << 2;
                xr_[r] = *(const float4*)(x + ((size_t)(b * C_ + ck * 32 + cc)) * N_ + n0 + nv);
            }
        };
        auto sts_chunk = [&](int ck, float4 (&xr_)[4]) {
#pragma unroll
            for (int r = 0; r < 4; r++) {
                int idx = tid + r * 256;
                int cc = idx >> 5, nv = (idx & 31) << 2;
                float4 v = xr_[r];
                uint32_t base = PJ_X + (uint32_t)(ck * 32 + cc) * PITCH + nv * 2;
                *(uint32_t*)(smem + base)     = h2pair(v.x, v.y);
                *(uint32_t*)(smem + base + 4) = h2pair(v.z, v.w);
            }
        };
        ldg_chunk(0, xr[0]);
#pragma unroll
        for (int ck = 0; ck < 8; ck++) {
            if (ck < 7) ldg_chunk(ck + 1, xr[(ck + 1) & 1]);
            sts_chunk(ck, xr[ck & 1]);
        }
    }
    CP_WAIT0();
    __syncthreads();
    load_w(1, 1);   // overlaps z=0 compute

    const uint32_t xa_off = (uint32_t)((lane & 7) + ((lane >> 4) << 3)) * PITCH
                          + (uint32_t)(wid * 16 + (((lane >> 3) & 1) << 3)) * 2;
    const uint32_t wb4 = (uint32_t)(lane & 7) * PJ_PW + ((lane >> 3) & 1) * 16
                       + (uint32_t)(lane >> 4) * (8 * PJ_PW);
    const size_t row0 = (size_t)b * N_ + n0 + wid * 16 + (lane >> 2);

#pragma unroll
    for (int z = 0; z < 3; z++) {
        const float* bias = (z == 0) ? bt : (z == 1) ? bp : bg;
        __half* outp = (z == 0) ? d_th : (z == 1) ? d_ph : d_g;
        const float osc = (z == 0) ? LOG2E : 1.f;
        const uint32_t wbase = sb + PJ_W + (uint32_t)(z & 1) * PJ_WBUF + wb4;

        float acc[16][4];
#pragma unroll
        for (int t = 0; t < 16; t++)
#pragma unroll
            for (int i = 0; i < 4; i++) acc[t][i] = 0.f;

#pragma unroll
        for (int ck = 0; ck < 8; ck++) {
            const uint32_t xb = sb + PJ_X + (uint32_t)ck * (32 * PITCH) + xa_off;
#pragma unroll
            for (int s = 0; s < 2; s++) {
                uint32_t ah[4];
                LDSM4T(ah[0], ah[1], ah[2], ah[3], xb + s * (16 * PITCH));
                const uint32_t wcol = wbase + (uint32_t)(ck * 32 + s * 16) * 2;
#pragma unroll
                for (int jb2 = 0; jb2 < 8; jb2++) {
                    uint32_t b0, b1, b2, b3;
                    LDSM4(b0, b1, b2, b3, wcol + jb2 * (16 * PJ_PW));
                    MMAF16(acc[2 * jb2],     ah, b0, b1);
                    MMAF16(acc[2 * jb2 + 1], ah, b2, b3);
                }
            }
        }

#pragma unroll
        for (int jb = 0; jb < 16; jb++) {
            const int o = jb * 8 + 2 * (lane & 3);
            float2 b2 = *(const float2*)(bias + o);
            *(uint32_t*)(outp + row0 * O_ + o)       = h2pair((acc[jb][0] + b2.x) * osc, (acc[jb][1] + b2.y) * osc);
            *(uint32_t*)(outp + (row0 + 8) * O_ + o) = h2pair((acc[jb][2] + b2.x) * osc, (acc[jb][3] + b2.y) * osc);
        }

        if (z < 2) {
            CP_WAIT0();
            __syncthreads();
            if (z == 0) load_w(2, 0);
        }
    }
}

// ---------------------------------------------------------------------------
// Kernel 2: fp16 flash attention.  BM=128, 4 warps x 32 q-rows, 2 CTAs/SM
// (desyncs softmax phases across CTAs so tensor/smem stay busy).
// Triple-buffered K/V (one barrier per tile); warp-vote rescale skip.
// QK fp32-acc; softmax base-2 (ex2.f16x2); l via ones-MMA; PV fp16-acc.
// grid (32 q-tiles, 8 b), 128 threads.
// ---------------------------------------------------------------------------
#define BKA 64
#define NTA (N_ / BKA)
#define KBUF   17408
#define AK_OFF 0
#define AV_OFF (3 * KBUF)
#define ATTN_SMEM (6 * KBUF)

__global__ __launch_bounds__(128, 2) void attn_kernel()
{
    extern __shared__ __align__(128) char smem[];
    const uint32_t sb = smem_u32(smem);
    const int tid = threadIdx.x;
    const int wid = tid >> 5, lane = tid & 31;
    const int b = blockIdx.y, q0 = blockIdx.x * 128;

    // Q fragments: 2 M-blocks x 8 k-steps (theta already *log2e)
    uint32_t qh[2][8][4];
#pragma unroll
    for (int mb = 0; mb < 2; mb++) {
        const __half* Th = d_th + ((size_t)b * N_ + q0 + wid * 32 + mb * 16 + (lane >> 2)) * O_;
        const int c0 = 2 * (lane & 3);
#pragma unroll
        for (int s = 0; s < 8; s++) {
            qh[mb][s][0] = *(const uint32_t*)(Th + s * 16 + c0);
            qh[mb][s][1] = *(const uint32_t*)(Th + 8 * O_ + s * 16 + c0);
            qh[mb][s][2] = *(const uint32_t*)(Th + s * 16 + c0 + 8);
            qh[mb][s][3] = *(const uint32_t*)(Th + 8 * O_ + s * 16 + c0 + 8);
        }
    }

    const __half* Ph = d_ph + (size_t)b * N_ * O_;
    const __half* Vh = d_g  + (size_t)b * N_ * O_;

    const uint32_t kb4 = sb + AK_OFF + (lane & 7) * PITCH + ((lane >> 3) & 1) * 16
                       + (lane >> 4) * (8 * PITCH);
    const uint32_t vb4 = sb + AV_OFF + (lane & 7) * PITCH + ((lane >> 3) & 1) * (8 * PITCH)
                       + (lane >> 4) * 16;

    uint32_t acc2[2][16][2];   // fp16x2 accumulators
#pragma unroll
    for (int mb = 0; mb < 2; mb++)
#pragma unroll
        for (int k = 0; k < 16; k++) { acc2[mb][k][0] = 0u; acc2[mb][k][1] = 0u; }
    float lacc[2][4];
#pragma unroll
    for (int mb = 0; mb < 2; mb++)
#pragma unroll
        for (int i = 0; i < 4; i++) lacc[mb][i] = 0.f;
    float m0[2] = {-1e30f, -1e30f}, m1[2] = {-1e30f, -1e30f};

    auto load_tile = [&](int jt) {
        const size_t k0 = (size_t)jt * BKA;
        const uint32_t slot = (uint32_t)(jt % 3) * KBUF;
#pragma unroll
        for (int r = 0; r < 8; r++) {
            int idx = tid + r * 128;
            int k = idx >> 4, ch = idx & 15;
            uint32_t off = slot + (uint32_t)k * PITCH + ch * 16;
            const size_t g = (k0 + k) * O_ + ch * 8;
            CP16(sb + AK_OFF + off, Ph + g);
            CP16(sb + AV_OFF + off, Vh + g);
        }
    };

    load_tile(0);
    CP_COMMIT();

    for (int j = 0; j < NTA; j++) {
        const uint32_t slot = (uint32_t)(j % 3) * KBUF;
        if (j + 1 < NTA) { load_tile(j + 1); CP_COMMIT(); CP_WAIT1(); }
        else            { CP_WAIT0(); }
        __syncthreads();

        // S = Q K^T, fp32 acc (base-2 logits).  S[mb*8+nb]
        float S[16][4];
#pragma unroll
        for (int i = 0; i < 16; i++)
#pragma unroll
            for (int q = 0; q < 4; q++) S[i][q] = 0.f;
        const uint32_t kb = kb4 + slot;
#pragma unroll
        for (int s = 0; s < 8; s++) {
#pragma unroll
            for (int jb2 = 0; jb2 < 4; jb2++) {
                uint32_t b0, b1, b2, b3;
                LDSM4(b0, b1, b2, b3, kb + jb2 * (16 * PITCH) + s * 32);
                MMAF16(S[2 * jb2],         qh[0][s], b0, b1);
                MMAF16(S[2 * jb2 + 1],     qh[0][s], b2, b3);
                MMAF16(S[8 + 2 * jb2],     qh[1][s], b0, b1);
                MMAF16(S[8 + 2 * jb2 + 1], qh[1][s], b2, b3);
            }
        }

        // softmax (base 2), per M-block; rescale skipped when max unchanged
        uint32_t ah[2][4][4];
#pragma unroll
        for (int mb = 0; mb < 2; mb++) {
            float mt0 = S[mb * 8][0], mt1 = S[mb * 8][2];
#pragma unroll
            for (int nb = 0; nb < 8; nb++) {
                mt0 = fmaxf(mt0, fmaxf(S[mb * 8 + nb][0], S[mb * 8 + nb][1]));
                mt1 = fmaxf(mt1, fmaxf(S[mb * 8 + nb][2], S[mb * 8 + nb][3]));
            }
            mt0 = fmaxf(mt0, __shfl_xor_sync(0xffffffffu, mt0, 1));
            mt0 = fmaxf(mt0, __shfl_xor_sync(0xffffffffu, mt0, 2));
            mt1 = fmaxf(mt1, __shfl_xor_sync(0xffffffffu, mt1, 1));
            mt1 = fmaxf(mt1, __shfl_xor_sync(0xffffffffu, mt1, 2));
            float mn0 = fmaxf(m0[mb], mt0), mn1 = fmaxf(m1[mb], mt1);
            float sc0 = exp2f(m0[mb] - mn0), sc1 = exp2f(m1[mb] - mn1);
            m0[mb] = mn0; m1[mb] = mn1;
            if (!__all_sync(0xffffffffu, (sc0 == 1.f) && (sc1 == 1.f))) {
                uint32_t scp0 = h2pair(sc0, sc0), scp1 = h2pair(sc1, sc1);
#pragma unroll
                for (int k = 0; k < 16; k++) {
                    HMUL2(acc2[mb][k][0], scp0);
                    HMUL2(acc2[mb][k][1], scp1);
                }
                lacc[mb][0] *= sc0; lacc[mb][1] *= sc0;
                lacc[mb][2] *= sc1; lacc[mb][3] *= sc1;
            }
#pragma unroll
            for (int nb = 0; nb < 8; nb++) {
                const int i = mb * 8 + nb;
                uint32_t p0 = h2pair(S[i][0] - mn0, S[i][1] - mn0);
                uint32_t p1 = h2pair(S[i][2] - mn1, S[i][3] - mn1);
                EX2H2(p0);
                EX2H2(p1);
                ah[mb][nb >> 1][(nb & 1) * 2]     = p0;
                ah[mb][nb >> 1][(nb & 1) * 2 + 1] = p1;
            }
        }

        // PV (fp16 acc) + row sums via ones-MMA (fp32 acc)
        const uint32_t vb = vb4 + slot;
#pragma unroll
        for (int s2 = 0; s2 < 4; s2++) {
            MMAF16(lacc[0], ah[0][s2], ONESH2, ONESH2);
            MMAF16(lacc[1], ah[1][s2], ONESH2, ONESH2);
#pragma unroll
            for (int t2 = 0; t2 < 8; t2++) {
                uint32_t v0, v1, v2, v3;
                LDSM4T(v0, v1, v2, v3, vb + s2 * (16 * PITCH) + t2 * 32);
                MMAH(acc2[0][2 * t2],     ah[0][s2], v0, v1);
                MMAH(acc2[0][2 * t2 + 1], ah[0][s2], v2, v3);
                MMAH(acc2[1][2 * t2],     ah[1][s2], v0, v1);
                MMAH(acc2[1][2 * t2 + 1], ah[1][s2], v2, v3);
            }
        }
        // no bottom barrier: triple-buffered slots keep writes disjoint.
    }

    // epilogue: normalize by l (from ones-MMA), store y fp16
#pragma unroll
    for (int mb = 0; mb < 2; mb++) {
        const float inv0 = 1.f / lacc[mb][0];
        const float inv1 = 1.f / lacc[mb][2];
        const size_t row = (size_t)b * N_ + q0 + wid * 32 + mb * 16 + (lane >> 2);
#pragma unroll
        for (int k = 0; k < 16; k++) {
            const int col = (k >> 1) * 16 + (k & 1) * 8 + 2 * (lane & 3);
            __half2 h0 = *(__half2*)&acc2[mb][k][0];
            __half2 h1 = *(__half2*)&acc2[mb][k][1];
            *(uint32_t*)(d_y16 + row * O_ + col) =
                h2pair(__low2float(h0) * inv0, __high2float(h0) * inv0);
            *(uint32_t*)(d_y16 + (row + 8) * O_ + col) =
                h2pair(__low2float(h1) * inv1, __high2float(h1) * inv1);
        }
    }
}

// ---------------------------------------------------------------------------
// Kernel 3: out = x + BN(W_out y + b_out), single fp16 GEMM.
// Tile 64c x 128n, 128 threads, 2 CTAs/SM.  grid (32 n, 4 c, 8 b).
// ---------------------------------------------------------------------------
#define OK_WH 0
#define OK_YH 17408
#define OUT_SMEM 52224

__global__ __launch_bounds__(128, 2) void out_kernel(
    const float* __restrict__ x,
    const float* __restrict__ wo, const float* __restrict__ bo,
    const float* __restrict__ gamma, const float* __restrict__ beta,
    const float* __restrict__ mean, const float* __restrict__ var,
    float* __restrict__ out)
{
    extern __shared__ __align__(128) char smem[];
    const uint32_t sb = smem_u32(smem);
    const int tid = threadIdx.x;
    const int wid = tid >> 5, lane = tid & 31;
    const int b = blockIdx.z, c0 = blockIdx.y * 64, n0 = blockIdx.x * 128;

#pragma unroll
    for (int r = 0; r < 8; r++) {
        int idx = tid + r * 128;
        int row = idx >> 3, ch = idx & 7;
        const size_t g = ((size_t)b * N_ + n0 + row) * O_ + ch * 16;
        uint32_t off = (uint32_t)row * PITCH + ch * 32;
        CP16(sb + OK_YH + off,      d_y16 + g);
        CP16(sb + OK_YH + off + 16, d_y16 + g + 8);
    }
    CP_COMMIT();

#pragma unroll
    for (int r = 0; r < 16; r++) {
        int idx = tid + r * 128;
        int c = idx >> 5, ov = (idx & 31) << 2;
        float4 w = *(const float4*)(wo + (size_t)(c0 + c) * O_ + ov);
        uint32_t off = (uint32_t)c * PITCH + ov * 2;
        *(uint32_t*)(smem + OK_WH + off)     = h2pair(w.x, w.y);
        *(uint32_t*)(smem + OK_WH + off + 4) = h2pair(w.z, w.w);
    }
    CP_WAIT0();
    __syncthreads();

    float acc[16][4];
#pragma unroll
    for (int t = 0; t < 16; t++)
#pragma unroll
        for (int i = 0; i < 4; i++) acc[t][i] = 0.f;

    const uint32_t wa  = sb + OK_WH + (uint32_t)(wid * 16 + (lane & 15)) * PITCH + ((lane >> 4) & 1) * 16;
    const uint32_t yb4 = sb + OK_YH + (lane & 7) * PITCH + ((lane >> 3) & 1) * 16
                       + (lane >> 4) * (8 * PITCH);

#pragma unroll
    for (int s = 0; s < 8; s++) {
        uint32_t ahf[4];
        LDSM4(ahf[0], ahf[1], ahf[2], ahf[3], wa + s * 32);
#pragma unroll
        for (int jb2 = 0; jb2 < 8; jb2++) {
            uint32_t y0, y1, y2, y3;
            LDSM4(y0, y1, y2, y3, yb4 + jb2 * (16 * PITCH) + s * 32);
            MMAF16(acc[2 * jb2],     ahf, y0, y1);
            MMAF16(acc[2 * jb2 + 1], ahf, y2, y3);
        }
    }

    const int cr0 = c0 + wid * 16 + (lane >> 2);
#pragma unroll
    for (int h = 0; h < 2; h++) {
        const int c = cr0 + h * 8;
        const float inv = gamma[c] * rsqrtf(var[c] + 1e-5f);
        const float sh = beta[c] - mean[c] * inv + bo[c] * inv;
        const size_t rb = ((size_t)(b * C_ + c)) * N_ + n0 + 2 * (lane & 3);
#pragma unroll
        for (int jb = 0; jb < 16; jb++) {
            float2 xv = *(const float2*)(x + rb + jb * 8);
            float2 ov;
            ov.x = xv.x + acc[jb][2 * h + 0] * inv + sh;
            ov.y = xv.y + acc[jb][2 * h + 1] * inv + sh;
            *(float2*)(out + rb + jb * 8) = ov;
        }
    }
}

// ---------------------------------------------------------------------------
extern "C" void kernel_launch(void* const* d_in, const int* in_sizes, int n_in,
                              void* d_out, int out_size)
{
    const float* x     = (const float*)d_in[0];
    const float* wt    = (const float*)d_in[1];
    const float* bt    = (const float*)d_in[2];
    const float* wp    = (const float*)d_in[3];
    const float* bp    = (const float*)d_in[4];
    const float* wg    = (const float*)d_in[5];
    const float* bg    = (const float*)d_in[6];
    const float* wo    = (const float*)d_in[7];
    const float* bo    = (const float*)d_in[8];
    const float* gamma = (const float*)d_in[9];
    const float* beta  = (const float*)d_in[10];
    const float* mean  = (const float*)d_in[11];
    const float* var   = (const float*)d_in[12];
    float* out = (float*)d_out;

    cudaFuncSetAttribute(proj_kernel, cudaFuncAttributeMaxDynamicSharedMemorySize, PROJ_SMEM);
    cudaFuncSetAttribute(attn_kernel, cudaFuncAttributeMaxDynamicSharedMemorySize, ATTN_SMEM);
    cudaFuncSetAttribute(out_kernel,  cudaFuncAttributeMaxDynamicSharedMemorySize, OUT_SMEM);

    setup_kernel<<<3, 256>>>(wt, wp, wg);
    proj_kernel<<<dim3(32, 8), 256, PROJ_SMEM>>>(x, bt, bp, bg);
    attn_kernel<<<dim3(32, 8), 128, ATTN_SMEM>>>();
    out_kernel<<<dim3(32, 4, 8), 128, OUT_SMEM>>>(x, wo, bo, gamma, beta, mean, var, out);
}

// round 16
// speedup vs baseline: 1.2299x; 1.0049x over previous
#include <cuda_runtime.h>
#include <cuda_fp16.h>
#include <cstdint>
#include <math.h>

#define B_ 8
#define C_ 256
#define N_ 4096
#define O_ 128

// Scratch (__device__ globals: allocation-free rule).
__device__ __half d_th [(size_t)B_ * N_ * O_];   // theta * log2(e), fp16
__device__ __half d_ph [(size_t)B_ * N_ * O_];
__device__ __half d_g  [(size_t)B_ * N_ * O_];
__device__ __half d_w16[4 * O_ * C_];            // wt, wp, wg, w_out (fp16)

__device__ __forceinline__ uint32_t smem_u32(const void* p) {
    uint32_t a;
    asm("{ .reg .u64 t; cvta.to.shared.u64 t, %1; cvt.u32.u64 %0, t; }" : "=r"(a) : "l"(p));
    return a;
}

#define MMAF16(c, a, b0v, b1v) asm volatile( \
    "mma.sync.aligned.m16n8k16.row.col.f32.f16.f16.f32 " \
    "{%0,%1,%2,%3}, {%4,%5,%6,%7}, {%8,%9}, {%0,%1,%2,%3};" \
    : "+f"((c)[0]), "+f"((c)[1]), "+f"((c)[2]), "+f"((c)[3]) \
    : "r"((a)[0]), "r"((a)[1]), "r"((a)[2]), "r"((a)[3]), "r"(b0v), "r"(b1v))

// fp16-accumulator MMA (C/D are 2 x fp16x2 regs)
#define MMAH(c, a, b0v, b1v) asm volatile( \
    "mma.sync.aligned.m16n8k16.row.col.f16.f16.f16.f16 " \
    "{%0,%1}, {%2,%3,%4,%5}, {%6,%7}, {%0,%1};" \
    : "+r"((c)[0]), "+r"((c)[1]) \
    : "r"((a)[0]), "r"((a)[1]), "r"((a)[2]), "r"((a)[3]), "r"(b0v), "r"(b1v))

#define LDSM4(r0, r1, r2, r3, addr)  asm volatile("ldmatrix.sync.aligned.m8n8.x4.shared.b16 {%0,%1,%2,%3}, [%4];" : "=r"(r0), "=r"(r1), "=r"(r2), "=r"(r3) : "r"(addr))
#define LDSM4T(r0, r1, r2, r3, addr) asm volatile("ldmatrix.sync.aligned.m8n8.x4.trans.shared.b16 {%0,%1,%2,%3}, [%4];" : "=r"(r0), "=r"(r1), "=r"(r2), "=r"(r3) : "r"(addr))
#define CP16(dst, src)   asm volatile("cp.async.cg.shared.global [%0], [%1], 16;" :: "r"(dst), "l"(src))
#define CP_COMMIT()      asm volatile("cp.async.commit_group;" ::: "memory")
#define CP_WAIT0()       asm volatile("cp.async.wait_group 0;" ::: "memory")
#define CP_WAIT1()       asm volatile("cp.async.wait_group 1;" ::: "memory")
#define EX2H2(r)         asm("ex2.approx.f16x2 %0, %0;" : "+r"(r))
#define HMUL2(d, s)      asm("mul.rn.f16x2 %0, %0, %1;" : "+r"(d) : "r"(s))

__device__ __forceinline__ uint32_t h2pair(float a, float b) {
    uint32_t r;
    asm("cvt.rn.f16x2.f32 %0, %1, %2;" : "=r"(r) : "f"(b), "f"(a));
    return r;
}

#define PITCH 272
#define LOG2E 1.4426950408889634f
#define ONESH2 0x3C003C00u

// ---------------------------------------------------------------------------
// Kernel 0: all four weight matrices -> fp16 once.
// ---------------------------------------------------------------------------
__global__ void setup_kernel(const float* __restrict__ wt,
                             const float* __restrict__ wp,
                             const float* __restrict__ wg,
                             const float* __restrict__ wo)
{
    const int z = blockIdx.x;
    const float* W = (z == 0) ? wt : (z == 1) ? wp : (z == 2) ? wg : wo;
    __half* out = d_w16 + (size_t)z * O_ * C_;
    for (int i = threadIdx.x; i < O_ * C_ / 4; i += blockDim.x) {
        float4 w = *(const float4*)(W + i * 4);
        *(uint32_t*)(out + i * 4)     = h2pair(w.x, w.y);
        *(uint32_t*)(out + i * 4 + 2) = h2pair(w.z, w.w);
    }
}

// ---------------------------------------------------------------------------
// Kernel 1: FUSED projections (x tile loaded once, W double-buffered).
// grid (32 n, 8 b), 256 thr.
// ---------------------------------------------------------------------------
#define PJ_X   0
#define PJ_W   69632
#define PJ_WBUF 67584
#define PJ_PW  528
#define PROJ_SMEM (69632 + 2 * 67584)

__global__ __launch_bounds__(256, 1) void proj_kernel(
    const float* __restrict__ x,
    const float* __restrict__ bt, const float* __restrict__ bp,
    const float* __restrict__ bg)
{
    extern __shared__ __align__(128) char smem[];
    const uint32_t sb = smem_u32(smem);
    const int tid = threadIdx.x;
    const int wid = tid >> 5, lane = tid & 31;
    const int b = blockIdx.y, n0 = blockIdx.x * 128;

    auto load_w = [&](int z, int buf) {
        const __half* Wg = d_w16 + (size_t)z * O_ * C_;
        const uint32_t base = PJ_W + (uint32_t)buf * PJ_WBUF;
#pragma unroll
        for (int r = 0; r < 16; r++) {
            int idx = tid + r * 256;
            int o = idx >> 5, ch = idx & 31;
            CP16(sb + base + (uint32_t)o * PJ_PW + ch * 16, Wg + (size_t)o * C_ + ch * 8);
        }
        CP_COMMIT();
    };

    load_w(0, 0);

    {
        float4 xr[2][4];
        auto ldg_chunk = [&](int ck, float4 (&xr_)[4]) {
#pragma unroll
            for (int r = 0; r < 4; r++) {
                int idx = tid + r * 256;
                int cc = idx >> 5, nv = (idx & 31) << 2;
                xr_[r] = *(const float4*)(x + ((size_t)(b * C_ + ck * 32 + cc)) * N_ + n0 + nv);
            }
        };
        auto sts_chunk = [&](int ck, float4 (&xr_)[4]) {
#pragma unroll
            for (int r = 0; r < 4; r++) {
                int idx = tid + r * 256;
                int cc = idx >> 5, nv = (idx & 31) << 2;
                float4 v = xr_[r];
                uint32_t base = PJ_X + (uint32_t)(ck * 32 + cc) * PITCH + nv * 2;
                *(uint32_t*)(smem + base)     = h2pair(v.x, v.y);
                *(uint32_t*)(smem + base + 4) = h2pair(v.z, v.w);
            }
        };
        ldg_chunk(0, xr[0]);
#pragma unroll
        for (int ck = 0; ck < 8; ck++) {
            if (ck < 7) ldg_chunk(ck + 1, xr[(ck + 1) & 1]);
            sts_chunk(ck, xr[ck & 1]);
        }
    }
    CP_WAIT0();
    __syncthreads();
    load_w(1, 1);   // overlaps z=0 compute

    const uint32_t xa_off = (uint32_t)((lane & 7) + ((lane >> 4) << 3)) * PITCH
                          + (uint32_t)(wid * 16 + (((lane >> 3) & 1) << 3)) * 2;
    const uint32_t wb4 = (uint32_t)(lane & 7) * PJ_PW + ((lane >> 3) & 1) * 16
                       + (uint32_t)(lane >> 4) * (8 * PJ_PW);
    const size_t row0 = (size_t)b * N_ + n0 + wid * 16 + (lane >> 2);

#pragma unroll
    for (int z = 0; z < 3; z++) {
        const float* bias = (z == 0) ? bt : (z == 1) ? bp : bg;
        __half* outp = (z == 0) ? d_th : (z == 1) ? d_ph : d_g;
        const float osc = (z == 0) ? LOG2E : 1.f;
        const uint32_t wbase = sb + PJ_W + (uint32_t)(z & 1) * PJ_WBUF + wb4;

        float acc[16][4];
#pragma unroll
        for (int t = 0; t < 16; t++)
#pragma unroll
            for (int i = 0; i < 4; i++) acc[t][i] = 0.f;

#pragma unroll
        for (int ck = 0; ck < 8; ck++) {
            const uint32_t xb = sb + PJ_X + (uint32_t)ck * (32 * PITCH) + xa_off;
#pragma unroll
            for (int s = 0; s < 2; s++) {
                uint32_t ah[4];
                LDSM4T(ah[0], ah[1], ah[2], ah[3], xb + s * (16 * PITCH));
                const uint32_t wcol = wbase + (uint32_t)(ck * 32 + s * 16) * 2;
#pragma unroll
                for (int jb2 = 0; jb2 < 8; jb2++) {
                    uint32_t b0, b1, b2, b3;
                    LDSM4(b0, b1, b2, b3, wcol + jb2 * (16 * PJ_PW));
                    MMAF16(acc[2 * jb2],     ah, b0, b1);
                    MMAF16(acc[2 * jb2 + 1], ah, b2, b3);
                }
            }
        }

#pragma unroll
        for (int jb = 0; jb < 16; jb++) {
            const int o = jb * 8 + 2 * (lane & 3);
            float2 b2 = *(const float2*)(bias + o);
            *(uint32_t*)(outp + row0 * O_ + o)       = h2pair((acc[jb][0] + b2.x) * osc, (acc[jb][1] + b2.y) * osc);
            *(uint32_t*)(outp + (row0 + 8) * O_ + o) = h2pair((acc[jb][2] + b2.x) * osc, (acc[jb][3] + b2.y) * osc);
        }

        if (z < 2) {
            CP_WAIT0();
            __syncthreads();
            if (z == 0) load_w(2, 0);
        }
    }
}

// ---------------------------------------------------------------------------
// Kernel 2: fp16 flash attention + FUSED output GEMM/BN/residual.
// BM=128, 4 warps x 32 q-rows, 2 CTAs/SM.  Triple-buffered K/V, one barrier
// per tile, warp-vote rescale skip.  After the mainloop the K/V smem is
// reused: y (fp16, 34KB) + W_out (fp16, 68KB); then out = x + BN(W_out y).
// grid (32 q-tiles, 8 b), 128 threads.
// ---------------------------------------------------------------------------
#define BKA 64
#define NTA (N_ / BKA)
#define KBUF   17408
#define AK_OFF 0
#define AV_OFF (3 * KBUF)
#define YOFF   0
#define WOFF   34816
#define ATTN_SMEM (6 * KBUF)

__global__ __launch_bounds__(128, 2) void attn_kernel(
    const float* __restrict__ x,
    const float* __restrict__ bo,
    const float* __restrict__ gamma, const float* __restrict__ beta,
    const float* __restrict__ mean, const float* __restrict__ var,
    float* __restrict__ out)
{
    extern __shared__ __align__(128) char smem[];
    const uint32_t sb = smem_u32(smem);
    const int tid = threadIdx.x;
    const int wid = tid >> 5, lane = tid & 31;
    const int b = blockIdx.y, q0 = blockIdx.x * 128;

    // Q fragments: 2 M-blocks x 8 k-steps (theta already *log2e)
    uint32_t qh[2][8][4];
#pragma unroll
    for (int mb = 0; mb < 2; mb++) {
        const __half* Th = d_th + ((size_t)b * N_ + q0 + wid * 32 + mb * 16 + (lane >> 2)) * O_;
        const int c0 = 2 * (lane & 3);
#pragma unroll
        for (int s = 0; s < 8; s++) {
            qh[mb][s][0] = *(const uint32_t*)(Th + s * 16 + c0);
            qh[mb][s][1] = *(const uint32_t*)(Th + 8 * O_ + s * 16 + c0);
            qh[mb][s][2] = *(const uint32_t*)(Th + s * 16 + c0 + 8);
            qh[mb][s][3] = *(const uint32_t*)(Th + 8 * O_ + s * 16 + c0 + 8);
        }
    }

    const __half* Ph = d_ph + (size_t)b * N_ * O_;
    const __half* Vh = d_g  + (size_t)b * N_ * O_;

    const uint32_t kb4 = sb + AK_OFF + (lane & 7) * PITCH + ((lane >> 3) & 1) * 16
                       + (lane >> 4) * (8 * PITCH);
    const uint32_t vb4 = sb + AV_OFF + (lane & 7) * PITCH + ((lane >> 3) & 1) * (8 * PITCH)
                       + (lane >> 4) * 16;

    uint32_t acc2[2][16][2];   // fp16x2 accumulators
#pragma unroll
    for (int mb = 0; mb < 2; mb++)
#pragma unroll
        for (int k = 0; k < 16; k++) { acc2[mb][k][0] = 0u; acc2[mb][k][1] = 0u; }
    float lacc[2][4];
#pragma unroll
    for (int mb = 0; mb < 2; mb++)
#pragma unroll
        for (int i = 0; i < 4; i++) lacc[mb][i] = 0.f;
    float m0[2] = {-1e30f, -1e30f}, m1[2] = {-1e30f, -1e30f};

    auto load_tile = [&](int jt) {
        const size_t k0 = (size_t)jt * BKA;
        const uint32_t slot = (uint32_t)(jt % 3) * KBUF;
#pragma unroll
        for (int r = 0; r < 8; r++) {
            int idx = tid + r * 128;
            int k = idx >> 4, ch = idx & 15;
            uint32_t off = slot + (uint32_t)k * PITCH + ch * 16;
            const size_t g = (k0 + k) * O_ + ch * 8;
            CP16(sb + AK_OFF + off, Ph + g);
            CP16(sb + AV_OFF + off, Vh + g);
        }
    };

    load_tile(0);
    CP_COMMIT();

    for (int j = 0; j < NTA; j++) {
        const uint32_t slot = (uint32_t)(j % 3) * KBUF;
        if (j + 1 < NTA) { load_tile(j + 1); CP_COMMIT(); CP_WAIT1(); }
        else            { CP_WAIT0(); }
        __syncthreads();

        // S = Q K^T, fp32 acc (base-2 logits).  S[mb*8+nb]
        float S[16][4];
#pragma unroll
        for (int i = 0; i < 16; i++)
#pragma unroll
            for (int q = 0; q < 4; q++) S[i][q] = 0.f;
        const uint32_t kb = kb4 + slot;
#pragma unroll
        for (int s = 0; s < 8; s++) {
#pragma unroll
            for (int jb2 = 0; jb2 < 4; jb2++) {
                uint32_t b0, b1, b2, b3;
                LDSM4(b0, b1, b2, b3, kb + jb2 * (16 * PITCH) + s * 32);
                MMAF16(S[2 * jb2],         qh[0][s], b0, b1);
                MMAF16(S[2 * jb2 + 1],     qh[0][s], b2, b3);
                MMAF16(S[8 + 2 * jb2],     qh[1][s], b0, b1);
                MMAF16(S[8 + 2 * jb2 + 1], qh[1][s], b2, b3);
            }
        }

        // softmax (base 2), per M-block; rescale skipped when max unchanged
        uint32_t ah[2][4][4];
#pragma unroll
        for (int mb = 0; mb < 2; mb++) {
            float mt0 = S[mb * 8][0], mt1 = S[mb * 8][2];
#pragma unroll
            for (int nb = 0; nb < 8; nb++) {
                mt0 = fmaxf(mt0, fmaxf(S[mb * 8 + nb][0], S[mb * 8 + nb][1]));
                mt1 = fmaxf(mt1, fmaxf(S[mb * 8 + nb][2], S[mb * 8 + nb][3]));
            }
            mt0 = fmaxf(mt0, __shfl_xor_sync(0xffffffffu, mt0, 1));
            mt0 = fmaxf(mt0, __shfl_xor_sync(0xffffffffu, mt0, 2));
            mt1 = fmaxf(mt1, __shfl_xor_sync(0xffffffffu, mt1, 1));
            mt1 = fmaxf(mt1, __shfl_xor_sync(0xffffffffu, mt1, 2));
            float mn0 = fmaxf(m0[mb], mt0), mn1 = fmaxf(m1[mb], mt1);
            float sc0 = exp2f(m0[mb] - mn0), sc1 = exp2f(m1[mb] - mn1);
            m0[mb] = mn0; m1[mb] = mn1;
            if (!__all_sync(0xffffffffu, (sc0 == 1.f) && (sc1 == 1.f))) {
                uint32_t scp0 = h2pair(sc0, sc0), scp1 = h2pair(sc1, sc1);
#pragma unroll
                for (int k = 0; k < 16; k++) {
                    HMUL2(acc2[mb][k][0], scp0);
                    HMUL2(acc2[mb][k][1], scp1);
                }
                lacc[mb][0] *= sc0; lacc[mb][1] *= sc0;
                lacc[mb][2] *= sc1; lacc[mb][3] *= sc1;
            }
#pragma unroll
            for (int nb = 0; nb < 8; nb++) {
                const int i = mb * 8 + nb;
                uint32_t p0 = h2pair(S[i][0] - mn0, S[i][1] - mn0);
                uint32_t p1 = h2pair(S[i][2] - mn1, S[i][3] - mn1);
                EX2H2(p0);
                EX2H2(p1);
                ah[mb][nb >> 1][(nb & 1) * 2]     = p0;
                ah[mb][nb >> 1][(nb & 1) * 2 + 1] = p1;
            }
        }

        // PV (fp16 acc) + row sums via ones-MMA (fp32 acc)
        const uint32_t vb = vb4 + slot;
#pragma unroll
        for (int s2 = 0; s2 < 4; s2++) {
            MMAF16(lacc[0], ah[0][s2], ONESH2, ONESH2);
            MMAF16(lacc[1], ah[1][s2], ONESH2, ONESH2);
#pragma unroll
            for (int t2 = 0; t2 < 8; t2++) {
                uint32_t v0, v1, v2, v3;
                LDSM4T(v0, v1, v2, v3, vb + s2 * (16 * PITCH) + t2 * 32);
                MMAH(acc2[0][2 * t2],     ah[0][s2], v0, v1);
                MMAH(acc2[0][2 * t2 + 1], ah[0][s2], v2, v3);
                MMAH(acc2[1][2 * t2],     ah[1][s2], v0, v1);
                MMAH(acc2[1][2 * t2 + 1], ah[1][s2], v2, v3);
            }
        }
        // no bottom barrier: triple-buffered slots keep writes disjoint.
    }

    // ---- fused output: reuse K/V smem for y (fp16) and W_out (fp16) ----
    __syncthreads();   // all warps done reading K/V slots

    // W_out [256 c][128 o] fp16 -> smem (256 rows x 16 chunks of 16B)
    {
        const __half* Wo = d_w16 + (size_t)3 * O_ * C_;
#pragma unroll
        for (int r = 0; r < 32; r++) {
            int idx = tid + r * 128;
            int c = idx >> 4, ch = idx & 15;
            CP16(sb + WOFF + (uint32_t)c * PITCH + ch * 16, Wo + (size_t)c * O_ + ch * 8);
        }
        CP_COMMIT();
    }

    // y = acc/l -> smem fp16 at YOFF (row-local layout [n][o], pitch 272)
#pragma unroll
    for (int mb = 0; mb < 2; mb++) {
        const float inv0 = 1.f / lacc[mb][0];
        const float inv1 = 1.f / lacc[mb][2];
        const uint32_t rowl = (uint32_t)(wid * 32 + mb * 16 + (lane >> 2));
#pragma unroll
        for (int k = 0; k < 16; k++) {
            const int col = (k >> 1) * 16 + (k & 1) * 8 + 2 * (lane & 3);
            __half2 h0 = *(__half2*)&acc2[mb][k][0];
            __half2 h1 = *(__half2*)&acc2[mb][k][1];
            *(uint32_t*)(smem + YOFF + rowl * PITCH + col * 2) =
                h2pair(__low2float(h0) * inv0, __high2float(h0) * inv0);
            *(uint32_t*)(smem + YOFF + (rowl + 8) * PITCH + col * 2) =
                h2pair(__low2float(h1) * inv1, __high2float(h1) * inv1);
        }
    }
    CP_WAIT0();
    __syncthreads();

    // out GEMM in 4 chunks of 64 c: out[c][n] = sum_o W[c][o] y[n][o]
    const uint32_t yb4 = sb + YOFF + (lane & 7) * PITCH + ((lane >> 3) & 1) * 16
                       + (lane >> 4) * (8 * PITCH);
#pragma unroll 1
    for (int chn = 0; chn < 4; chn++) {
        float acc[16][4];
#pragma unroll
        for (int t = 0; t < 16; t++)
#pragma unroll
            for (int i = 0; i < 4; i++) acc[t][i] = 0.f;

        const uint32_t wa = sb + WOFF
            + (uint32_t)(chn * 64 + wid * 16 + (lane & 15)) * PITCH
            + ((lane >> 4) & 1) * 16;

#pragma unroll
        for (int s = 0; s < 8; s++) {
            uint32_t ahf[4];
            LDSM4(ahf[0], ahf[1], ahf[2], ahf[3], wa + s * 32);
#pragma unroll
            for (int jb2 = 0; jb2 < 8; jb2++) {
                uint32_t y0, y1, y2, y3;
                LDSM4(y0, y1, y2, y3, yb4 + jb2 * (16 * PITCH) + s * 32);
                MMAF16(acc[2 * jb2],     ahf, y0, y1);
                MMAF16(acc[2 * jb2 + 1], ahf, y2, y3);
            }
        }

        const int cr0 = chn * 64 + wid * 16 + (lane >> 2);
#pragma unroll
        for (int h = 0; h < 2; h++) {
            const int c = cr0 + h * 8;
            const float inv = gamma[c] * rsqrtf(var[c] + 1e-5f);
            const float sh = beta[c] - mean[c] * inv + bo[c] * inv;
            const size_t rb = ((size_t)(b * C_ + c)) * N_ + q0 + 2 * (lane & 3);
#pragma unroll
            for (int jb = 0; jb < 16; jb++) {
                float2 xv = *(const float2*)(x + rb + jb * 8);
                float2 ov;
                ov.x = xv.x + acc[jb][2 * h + 0] * inv + sh;
                ov.y = xv.y + acc[jb][2 * h + 1] * inv + sh;
                *(float2*)(out + rb + jb * 8) = ov;
            }
        }
    }
}

// ---------------------------------------------------------------------------
extern "C" void kernel_launch(void* const* d_in, const int* in_sizes, int n_in,
                              void* d_out, int out_size)
{
    const float* x     = (const float*)d_in[0];
    const float* wt    = (const float*)d_in[1];
    const float* bt    = (const float*)d_in[2];
    const float* wp    = (const float*)d_in[3];
    const float* bp    = (const float*)d_in[4];
    const float* wg    = (const float*)d_in[5];
    const float* bg    = (const float*)d_in[6];
    const float* wo    = (const float*)d_in[7];
    const float* bo    = (const float*)d_in[8];
    const float* gamma = (const float*)d_in[9];
    const float* beta  = (const float*)d_in[10];
    const float* mean  = (const float*)d_in[11];
    const float* var   = (const float*)d_in[12];
    float* out = (float*)d_out;

    cudaFuncSetAttribute(proj_kernel, cudaFuncAttributeMaxDynamicSharedMemorySize, PROJ_SMEM);
    cudaFuncSetAttribute(attn_kernel, cudaFuncAttributeMaxDynamicSharedMemorySize, ATTN_SMEM);

    setup_kernel<<<4, 256>>>(wt, wp, wg, wo);
    proj_kernel<<<dim3(32, 8), 256, PROJ_SMEM>>>(x, bt, bp, bg);
    attn_kernel<<<dim3(32, 8), 128, ATTN_SMEM>>>(x, bo, gamma, beta, mean, var, out);
}

// round 17
// speedup vs baseline: 1.2464x; 1.0134x over previous
#include <cuda_runtime.h>
#include <cuda_fp16.h>
#include <cstdint>
#include <math.h>

#define B_ 8
#define C_ 256
#define N_ 4096
#define O_ 128

// Scratch (__device__ globals: allocation-free rule).
__device__ __half d_th [(size_t)B_ * N_ * O_];   // theta * log2(e), fp16
__device__ __half d_ph [(size_t)B_ * N_ * O_];
__device__ __half d_g  [(size_t)B_ * N_ * O_];
__device__ __half d_w16[4 * O_ * C_];            // wt, wp, wg, w_out (fp16)

__device__ __forceinline__ uint32_t smem_u32(const void* p) {
    uint32_t a;
    asm("{ .reg .u64 t; cvta.to.shared.u64 t, %1; cvt.u32.u64 %0, t; }" : "=r"(a) : "l"(p));
    return a;
}

#define MMAF16(c, a, b0v, b1v) asm volatile( \
    "mma.sync.aligned.m16n8k16.row.col.f32.f16.f16.f32 " \
    "{%0,%1,%2,%3}, {%4,%5,%6,%7}, {%8,%9}, {%0,%1,%2,%3};" \
    : "+f"((c)[0]), "+f"((c)[1]), "+f"((c)[2]), "+f"((c)[3]) \
    : "r"((a)[0]), "r"((a)[1]), "r"((a)[2]), "r"((a)[3]), "r"(b0v), "r"(b1v))

// fp16-accumulator MMA (C/D are 2 x fp16x2 regs)
#define MMAH(c, a, b0v, b1v) asm volatile( \
    "mma.sync.aligned.m16n8k16.row.col.f16.f16.f16.f16 " \
    "{%0,%1}, {%2,%3,%4,%5}, {%6,%7}, {%0,%1};" \
    : "+r"((c)[0]), "+r"((c)[1]) \
    : "r"((a)[0]), "r"((a)[1]), "r"((a)[2]), "r"((a)[3]), "r"(b0v), "r"(b1v))

#define LDSM4(r0, r1, r2, r3, addr)  asm volatile("ldmatrix.sync.aligned.m8n8.x4.shared.b16 {%0,%1,%2,%3}, [%4];" : "=r"(r0), "=r"(r1), "=r"(r2), "=r"(r3) : "r"(addr))
#define LDSM4T(r0, r1, r2, r3, addr) asm volatile("ldmatrix.sync.aligned.m8n8.x4.trans.shared.b16 {%0,%1,%2,%3}, [%4];" : "=r"(r0), "=r"(r1), "=r"(r2), "=r"(r3) : "r"(addr))
#define CP16(dst, src)   asm volatile("cp.async.cg.shared.global [%0], [%1], 16;" :: "r"(dst), "l"(src))
#define CP_COMMIT()      asm volatile("cp.async.commit_group;" ::: "memory")
#define CP_WAIT0()       asm volatile("cp.async.wait_group 0;" ::: "memory")
#define CP_WAIT1()       asm volatile("cp.async.wait_group 1;" ::: "memory")
#define EX2H2(r)         asm("ex2.approx.f16x2 %0, %0;" : "+r"(r))
#define HMUL2(d, s)      asm("mul.rn.f16x2 %0, %0, %1;" : "+r"(d) : "r"(s))

__device__ __forceinline__ uint32_t h2pair(float a, float b) {
    uint32_t r;
    asm("cvt.rn.f16x2.f32 %0, %1, %2;" : "=r"(r) : "f"(b), "f"(a));
    return r;
}

#define PITCH 272
#define LOG2E 1.4426950408889634f
#define ONESH2 0x3C003C00u

// ---------------------------------------------------------------------------
// Kernel 0: all four weight matrices -> fp16. 64 blocks (16 slices/matrix).
// ---------------------------------------------------------------------------
__global__ void setup_kernel(const float* __restrict__ wt,
                             const float* __restrict__ wp,
                             const float* __restrict__ wg,
                             const float* __restrict__ wo)
{
    const int z = blockIdx.x >> 4;
    const int slice = blockIdx.x & 15;
    const float* W = (z == 0) ? wt : (z == 1) ? wp : (z == 2) ? wg : wo;
    __half* out = d_w16 + (size_t)z * O_ * C_;
    const int per_slice = O_ * C_ / 4 / 16;   // 512 float4 per slice
    const int base = slice * per_slice;
    for (int i = threadIdx.x; i < per_slice; i += blockDim.x) {
        float4 w = *(const float4*)(W + (size_t)(base + i) * 4);
        *(uint32_t*)(out + (size_t)(base + i) * 4)     = h2pair(w.x, w.y);
        *(uint32_t*)(out + (size_t)(base + i) * 4 + 2) = h2pair(w.z, w.w);
    }
}

// ---------------------------------------------------------------------------
// Kernel 1: FUSED projections (x tile loaded once, W double-buffered).
// grid (32 n, 8 b), 256 thr.
// ---------------------------------------------------------------------------
#define PJ_X   0
#define PJ_W   69632
#define PJ_WBUF 67584
#define PJ_PW  528
#define PROJ_SMEM (69632 + 2 * 67584)

__global__ __launch_bounds__(256, 1) void proj_kernel(
    const float* __restrict__ x,
    const float* __restrict__ bt, const float* __restrict__ bp,
    const float* __restrict__ bg)
{
    extern __shared__ __align__(128) char smem[];
    const uint32_t sb = smem_u32(smem);
    const int tid = threadIdx.x;
    const int wid = tid >> 5, lane = tid & 31;
    const int b = blockIdx.y, n0 = blockIdx.x * 128;

    auto load_w = [&](int z, int buf) {
        const __half* Wg = d_w16 + (size_t)z * O_ * C_;
        const uint32_t base = PJ_W + (uint32_t)buf * PJ_WBUF;
#pragma unroll
        for (int r = 0; r < 16; r++) {
            int idx = tid + r * 256;
            int o = idx >> 5, ch = idx & 31;
            CP16(sb + base + (uint32_t)o * PJ_PW + ch * 16, Wg + (size_t)o * C_ + ch * 8);
        }
        CP_COMMIT();
    };

    load_w(0, 0);

    {
        float4 xr[2][4];
        auto ldg_chunk = [&](int ck, float4 (&xr_)[4]) {
#pragma unroll
            for (int r = 0; r < 4; r++) {
                int idx = tid + r * 256;
                int cc = idx >> 5, nv = (idx & 31) << 2;
                xr_[r] = *(const float4*)(x + ((size_t)(b * C_ + ck * 32 + cc)) * N_ + n0 + nv);
            }
        };
        auto sts_chunk = [&](int ck, float4 (&xr_)[4]) {
#pragma unroll
            for (int r = 0; r < 4; r++) {
                int idx = tid + r * 256;
                int cc = idx >> 5, nv = (idx & 31) << 2;
                float4 v = xr_[r];
                uint32_t base = PJ_X + (uint32_t)(ck * 32 + cc) * PITCH + nv * 2;
                *(uint32_t*)(smem + base)     = h2pair(v.x, v.y);
                *(uint32_t*)(smem + base + 4) = h2pair(v.z, v.w);
            }
        };
        ldg_chunk(0, xr[0]);
#pragma unroll
        for (int ck = 0; ck < 8; ck++) {
            if (ck < 7) ldg_chunk(ck + 1, xr[(ck + 1) & 1]);
            sts_chunk(ck, xr[ck & 1]);
        }
    }
    CP_WAIT0();
    __syncthreads();
    load_w(1, 1);   // overlaps z=0 compute

    const uint32_t xa_off = (uint32_t)((lane & 7) + ((lane >> 4) << 3)) * PITCH
                          + (uint32_t)(wid * 16 + (((lane >> 3) & 1) << 3)) * 2;
    const uint32_t wb4 = (uint32_t)(lane & 7) * PJ_PW + ((lane >> 3) & 1) * 16
                       + (uint32_t)(lane >> 4) * (8 * PJ_PW);
    const size_t row0 = (size_t)b * N_ + n0 + wid * 16 + (lane >> 2);

#pragma unroll
    for (int z = 0; z < 3; z++) {
        const float* bias = (z == 0) ? bt : (z == 1) ? bp : bg;
        __half* outp = (z == 0) ? d_th : (z == 1) ? d_ph : d_g;
        const float osc = (z == 0) ? LOG2E : 1.f;
        const uint32_t wbase = sb + PJ_W + (uint32_t)(z & 1) * PJ_WBUF + wb4;

        float acc[16][4];
#pragma unroll
        for (int t = 0; t < 16; t++)
#pragma unroll
            for (int i = 0; i < 4; i++) acc[t][i] = 0.f;

#pragma unroll
        for (int ck = 0; ck < 8; ck++) {
            const uint32_t xb = sb + PJ_X + (uint32_t)ck * (32 * PITCH) + xa_off;
#pragma unroll
            for (int s = 0; s < 2; s++) {
                uint32_t ah[4];
                LDSM4T(ah[0], ah[1], ah[2], ah[3], xb + s * (16 * PITCH));
                const uint32_t wcol = wbase + (uint32_t)(ck * 32 + s * 16) * 2;
#pragma unroll
                for (int jb2 = 0; jb2 < 8; jb2++) {
                    uint32_t b0, b1, b2, b3;
                    LDSM4(b0, b1, b2, b3, wcol + jb2 * (16 * PJ_PW));
                    MMAF16(acc[2 * jb2],     ah, b0, b1);
                    MMAF16(acc[2 * jb2 + 1], ah, b2, b3);
                }
            }
        }

#pragma unroll
        for (int jb = 0; jb < 16; jb++) {
            const int o = jb * 8 + 2 * (lane & 3);
            float2 b2 = *(const float2*)(bias + o);
            *(uint32_t*)(outp + row0 * O_ + o)       = h2pair((acc[jb][0] + b2.x) * osc, (acc[jb][1] + b2.y) * osc);
            *(uint32_t*)(outp + (row0 + 8) * O_ + o) = h2pair((acc[jb][2] + b2.x) * osc, (acc[jb][3] + b2.y) * osc);
        }

        if (z < 2) {
            CP_WAIT0();
            __syncthreads();
            if (z == 0) load_w(2, 0);
        }
    }
}

// ---------------------------------------------------------------------------
// Kernel 2: fp16 flash attention + FUSED output GEMM/BN/residual.
// BM=128, 4 warps x 32 q-rows, 2 CTAs/SM.  Triple-buffered K/V, one barrier
// per tile, warp-vote rescale skip.  After the mainloop the K/V smem is
// reused: y (fp16, 34KB) + W_out (fp16, 68KB); then out = x + BN(W_out y).
// grid (32 q-tiles, 8 b), 128 threads.
// ---------------------------------------------------------------------------
#define BKA 64
#define NTA (N_ / BKA)
#define KBUF   17408
#define AK_OFF 0
#define AV_OFF (3 * KBUF)
#define YOFF   0
#define WOFF   34816
#define ATTN_SMEM (6 * KBUF)

__global__ __launch_bounds__(128, 2) void attn_kernel(
    const float* __restrict__ x,
    const float* __restrict__ bo,
    const float* __restrict__ gamma, const float* __restrict__ beta,
    const float* __restrict__ mean, const float* __restrict__ var,
    float* __restrict__ out)
{
    extern __shared__ __align__(128) char smem[];
    const uint32_t sb = smem_u32(smem);
    const int tid = threadIdx.x;
    const int wid = tid >> 5, lane = tid & 31;
    const int b = blockIdx.y, q0 = blockIdx.x * 128;

    // Q fragments: 2 M-blocks x 8 k-steps (theta already *log2e)
    uint32_t qh[2][8][4];
#pragma unroll
    for (int mb = 0; mb < 2; mb++) {
        const __half* Th = d_th + ((size_t)b * N_ + q0 + wid * 32 + mb * 16 + (lane >> 2)) * O_;
        const int c0 = 2 * (lane & 3);
#pragma unroll
        for (int s = 0; s < 8; s++) {
            qh[mb][s][0] = *(const uint32_t*)(Th + s * 16 + c0);
            qh[mb][s][1] = *(const uint32_t*)(Th + 8 * O_ + s * 16 + c0);
            qh[mb][s][2] = *(const uint32_t*)(Th + s * 16 + c0 + 8);
            qh[mb][s][3] = *(const uint32_t*)(Th + 8 * O_ + s * 16 + c0 + 8);
        }
    }

    const __half* Ph = d_ph + (size_t)b * N_ * O_;
    const __half* Vh = d_g  + (size_t)b * N_ * O_;

    const uint32_t kb4 = sb + AK_OFF + (lane & 7) * PITCH + ((lane >> 3) & 1) * 16
                       + (lane >> 4) * (8 * PITCH);
    const uint32_t vb4 = sb + AV_OFF + (lane & 7) * PITCH + ((lane >> 3) & 1) * (8 * PITCH)
                       + (lane >> 4) * 16;

    uint32_t acc2[2][16][2];   // fp16x2 accumulators
#pragma unroll
    for (int mb = 0; mb < 2; mb++)
#pragma unroll
        for (int k = 0; k < 16; k++) { acc2[mb][k][0] = 0u; acc2[mb][k][1] = 0u; }
    float lacc[2][4];
#pragma unroll
    for (int mb = 0; mb < 2; mb++)
#pragma unroll
        for (int i = 0; i < 4; i++) lacc[mb][i] = 0.f;
    float m0[2] = {-1e30f, -1e30f}, m1[2] = {-1e30f, -1e30f};

    auto load_tile = [&](int jt) {
        const size_t k0 = (size_t)jt * BKA;
        const uint32_t slot = (uint32_t)(jt % 3) * KBUF;
#pragma unroll
        for (int r = 0; r < 8; r++) {
            int idx = tid + r * 128;
            int k = idx >> 4, ch = idx & 15;
            uint32_t off = slot + (uint32_t)k * PITCH + ch * 16;
            const size_t g = (k0 + k) * O_ + ch * 8;
            CP16(sb + AK_OFF + off, Ph + g);
            CP16(sb + AV_OFF + off, Vh + g);
        }
    };

    load_tile(0);
    CP_COMMIT();

    for (int j = 0; j < NTA; j++) {
        const uint32_t slot = (uint32_t)(j % 3) * KBUF;
        if (j + 1 < NTA) { load_tile(j + 1); CP_COMMIT(); CP_WAIT1(); }
        else            { CP_WAIT0(); }
        __syncthreads();

        // S = Q K^T, fp32 acc (base-2 logits).  S[mb*8+nb]
        float S[16][4];
#pragma unroll
        for (int i = 0; i < 16; i++)
#pragma unroll
            for (int q = 0; q < 4; q++) S[i][q] = 0.f;
        const uint32_t kb = kb4 + slot;
#pragma unroll
        for (int s = 0; s < 8; s++) {
#pragma unroll
            for (int jb2 = 0; jb2 < 4; jb2++) {
                uint32_t b0, b1, b2, b3;
                LDSM4(b0, b1, b2, b3, kb + jb2 * (16 * PITCH) + s * 32);
                MMAF16(S[2 * jb2],         qh[0][s], b0, b1);
                MMAF16(S[2 * jb2 + 1],     qh[0][s], b2, b3);
                MMAF16(S[8 + 2 * jb2],     qh[1][s], b0, b1);
                MMAF16(S[8 + 2 * jb2 + 1], qh[1][s], b2, b3);
            }
        }

        // softmax (base 2), per M-block; rescale skipped when max unchanged
        uint32_t ah[2][4][4];
#pragma unroll
        for (int mb = 0; mb < 2; mb++) {
            float mt0 = S[mb * 8][0], mt1 = S[mb * 8][2];
#pragma unroll
            for (int nb = 0; nb < 8; nb++) {
                mt0 = fmaxf(mt0, fmaxf(S[mb * 8 + nb][0], S[mb * 8 + nb][1]));
                mt1 = fmaxf(mt1, fmaxf(S[mb * 8 + nb][2], S[mb * 8 + nb][3]));
            }
            mt0 = fmaxf(mt0, __shfl_xor_sync(0xffffffffu, mt0, 1));
            mt0 = fmaxf(mt0, __shfl_xor_sync(0xffffffffu, mt0, 2));
            mt1 = fmaxf(mt1, __shfl_xor_sync(0xffffffffu, mt1, 1));
            mt1 = fmaxf(mt1, __shfl_xor_sync(0xffffffffu, mt1, 2));
            float mn0 = fmaxf(m0[mb], mt0), mn1 = fmaxf(m1[mb], mt1);
            float sc0 = exp2f(m0[mb] - mn0), sc1 = exp2f(m1[mb] - mn1);
            m0[mb] = mn0; m1[mb] = mn1;
            if (!__all_sync(0xffffffffu, (sc0 == 1.f) && (sc1 == 1.f))) {
                uint32_t scp0 = h2pair(sc0, sc0), scp1 = h2pair(sc1, sc1);
#pragma unroll
                for (int k = 0; k < 16; k++) {
                    HMUL2(acc2[mb][k][0], scp0);
                    HMUL2(acc2[mb][k][1], scp1);
                }
                lacc[mb][0] *= sc0; lacc[mb][1] *= sc0;
                lacc[mb][2] *= sc1; lacc[mb][3] *= sc1;
            }
#pragma unroll
            for (int nb = 0; nb < 8; nb++) {
                const int i = mb * 8 + nb;
                uint32_t p0 = h2pair(S[i][0] - mn0, S[i][1] - mn0);
                uint32_t p1 = h2pair(S[i][2] - mn1, S[i][3] - mn1);
                EX2H2(p0);
                EX2H2(p1);
                ah[mb][nb >> 1][(nb & 1) * 2]     = p0;
                ah[mb][nb >> 1][(nb & 1) * 2 + 1] = p1;
            }
        }

        // PV (fp16 acc) + row sums via ones-MMA (fp32 acc)
        const uint32_t vb = vb4 + slot;
#pragma unroll
        for (int s2 = 0; s2 < 4; s2++) {
            MMAF16(lacc[0], ah[0][s2], ONESH2, ONESH2);
            MMAF16(lacc[1], ah[1][s2], ONESH2, ONESH2);
#pragma unroll
            for (int t2 = 0; t2 < 8; t2++) {
                uint32_t v0, v1, v2, v3;
                LDSM4T(v0, v1, v2, v3, vb + s2 * (16 * PITCH) + t2 * 32);
                MMAH(acc2[0][2 * t2],     ah[0][s2], v0, v1);
                MMAH(acc2[0][2 * t2 + 1], ah[0][s2], v2, v3);
                MMAH(acc2[1][2 * t2],     ah[1][s2], v0, v1);
                MMAH(acc2[1][2 * t2 + 1], ah[1][s2], v2, v3);
            }
        }
        // no bottom barrier: triple-buffered slots keep writes disjoint.
    }

    // ---- fused output: reuse K/V smem for y (fp16) and W_out (fp16) ----
    __syncthreads();   // all warps done reading K/V slots

    // W_out [256 c][128 o] fp16 -> smem (256 rows x 16 chunks of 16B)
    {
        const __half* Wo = d_w16 + (size_t)3 * O_ * C_;
#pragma unroll
        for (int r = 0; r < 32; r++) {
            int idx = tid + r * 128;
            int c = idx >> 4, ch = idx & 15;
            CP16(sb + WOFF + (uint32_t)c * PITCH + ch * 16, Wo + (size_t)c * O_ + ch * 8);
        }
        CP_COMMIT();
    }

    // y = acc/l -> smem fp16 at YOFF (row-local layout [n][o], pitch 272)
#pragma unroll
    for (int mb = 0; mb < 2; mb++) {
        const float inv0 = 1.f / lacc[mb][0];
        const float inv1 = 1.f / lacc[mb][2];
        const uint32_t rowl = (uint32_t)(wid * 32 + mb * 16 + (lane >> 2));
#pragma unroll
        for (int k = 0; k < 16; k++) {
            const int col = (k >> 1) * 16 + (k & 1) * 8 + 2 * (lane & 3);
            __half2 h0 = *(__half2*)&acc2[mb][k][0];
            __half2 h1 = *(__half2*)&acc2[mb][k][1];
            *(uint32_t*)(smem + YOFF + rowl * PITCH + col * 2) =
                h2pair(__low2float(h0) * inv0, __high2float(h0) * inv0);
            *(uint32_t*)(smem + YOFF + (rowl + 8) * PITCH + col * 2) =
                h2pair(__low2float(h1) * inv1, __high2float(h1) * inv1);
        }
    }
    CP_WAIT0();
    __syncthreads();

    // out GEMM in 4 chunks of 64 c: out[c][n] = sum_o W[c][o] y[n][o]
    const uint32_t yb4 = sb + YOFF + (lane & 7) * PITCH + ((lane >> 3) & 1) * 16
                       + (lane >> 4) * (8 * PITCH);
#pragma unroll 1
    for (int chn = 0; chn < 4; chn++) {
        float acc[16][4];
#pragma unroll
        for (int t = 0; t < 16; t++)
#pragma unroll
            for (int i = 0; i < 4; i++) acc[t][i] = 0.f;

        const uint32_t wa = sb + WOFF
            + (uint32_t)(chn * 64 + wid * 16 + (lane & 15)) * PITCH
            + ((lane >> 4) & 1) * 16;

#pragma unroll
        for (int s = 0; s < 8; s++) {
            uint32_t ahf[4];
            LDSM4(ahf[0], ahf[1], ahf[2], ahf[3], wa + s * 32);
#pragma unroll
            for (int jb2 = 0; jb2 < 8; jb2++) {
                uint32_t y0, y1, y2, y3;
                LDSM4(y0, y1, y2, y3, yb4 + jb2 * (16 * PITCH) + s * 32);
                MMAF16(acc[2 * jb2],     ahf, y0, y1);
                MMAF16(acc[2 * jb2 + 1], ahf, y2, y3);
            }
        }

        const int cr0 = chn * 64 + wid * 16 + (lane >> 2);
#pragma unroll
        for (int h = 0; h < 2; h++) {
            const int c = cr0 + h * 8;
            const float inv = gamma[c] * rsqrtf(var[c] + 1e-5f);
            const float sh = beta[c] - mean[c] * inv + bo[c] * inv;
            const size_t rb = ((size_t)(b * C_ + c)) * N_ + q0 + 2 * (lane & 3);
#pragma unroll
            for (int jb = 0; jb < 16; jb++) {
                float2 xv = *(const float2*)(x + rb + jb * 8);
                float2 ov;
                ov.x = xv.x + acc[jb][2 * h + 0] * inv + sh;
                ov.y = xv.y + acc[jb][2 * h + 1] * inv + sh;
                *(float2*)(out + rb + jb * 8) = ov;
            }
        }
    }
}

// ---------------------------------------------------------------------------
extern "C" void kernel_launch(void* const* d_in, const int* in_sizes, int n_in,
                              void* d_out, int out_size)
{
    const float* x     = (const float*)d_in[0];
    const float* wt    = (const float*)d_in[1];
    const float* bt    = (const float*)d_in[2];
    const float* wp    = (const float*)d_in[3];
    const float* bp    = (const float*)d_in[4];
    const float* wg    = (const float*)d_in[5];
    const float* bg    = (const float*)d_in[6];
    const float* wo    = (const float*)d_in[7];
    const float* bo    = (const float*)d_in[8];
    const float* gamma = (const float*)d_in[9];
    const float* beta  = (const float*)d_in[10];
    const float* mean  = (const float*)d_in[11];
    const float* var   = (const float*)d_in[12];
    float* out = (float*)d_out;

    cudaFuncSetAttribute(proj_kernel, cudaFuncAttributeMaxDynamicSharedMemorySize, PROJ_SMEM);
    cudaFuncSetAttribute(attn_kernel, cudaFuncAttributeMaxDynamicSharedMemorySize, ATTN_SMEM);

    setup_kernel<<<64, 256>>>(wt, wp, wg, wo);
    proj_kernel<<<dim3(32, 8), 256, PROJ_SMEM>>>(x, bt, bp, bg);
    attn_kernel<<<dim3(32, 8), 128, ATTN_SMEM>>>(x, bo, gamma, beta, mean, var, out);
}